// round 2
// baseline (speedup 1.0000x reference)
#include <cuda_runtime.h>
#include <cstdint>
#include <cstddef>

// ---------------- problem constants ----------------
#define NA 50000
#define NB 50000
#define NC 50000
#define EDG 800000
#define DIN 256
#define DOUT 128
#define SZ (50000 * 128)   // floats per [N,128] buffer

// ---------------- scratch (device global, no runtime alloc) ----------------
// layout (floats):
//  [0]  nbb   (NA*128)   -- spmm dst, must be zeroed
//  [1]  nbc   (NA*128)   -- spmm dst, must be zeroed
//  [2]  aggb  (NB*128)   -- spmm dst, must be zeroed
//  [3]  aggc  (NC*128)   -- spmm dst, must be zeroed
//  [4]  selfa
//  [5]  xbWab
//  [6]  xcWac
//  [7]  xaWba
//  [8]  xaWca
//  [9]  selfb
//  [10] selfc
//  [11] agga
//  then uv[256]
__device__ float g_scratch[12ull * SZ + 256];

// ---------------- SGEMM: Y[N,128] = X[N,256] @ W[256,128] (+bias) ----------
// split==0: X is [N,256] row-major.
// split==1: first 128 K from X ([N,128]), last 128 K from Xb ([N,128]).
#define BM 64
#define BN 128
#define BK 16

__global__ void __launch_bounds__(256) sgemm_k256(
    const float* __restrict__ X, const float* __restrict__ Xb,
    const float* __restrict__ W, const float* __restrict__ bias,
    float* __restrict__ Y, int N, int split)
{
    __shared__ float As[BK][BM + 4];   // pad to keep 16B alignment, reduce conflicts
    __shared__ float Bs[BK][BN];

    const int bm  = blockIdx.x * BM;
    const int tid = threadIdx.x;
    const int tx  = tid & 31;   // 32 groups of 4 output cols
    const int ty  = tid >> 5;   // 8 groups of 8 output rows

    float acc[8][4];
    #pragma unroll
    for (int i = 0; i < 8; i++)
        #pragma unroll
        for (int j = 0; j < 4; j++) acc[i][j] = 0.f;

    for (int k0 = 0; k0 < 256; k0 += BK) {
        // ---- load A tile: 64 rows x 16 k ----
        {
            const float* src;
            int ld, kcol;
            if (!split) { src = X; ld = 256; kcol = k0; }
            else {
                src = (k0 < 128) ? X : Xb;
                ld = 128; kcol = k0 & 127;
            }
            int r  = tid >> 2;          // 0..63
            int c4 = (tid & 3) * 4;     // 0,4,8,12
            int row = bm + r;
            float4 a = make_float4(0.f, 0.f, 0.f, 0.f);
            if (row < N)
                a = *(const float4*)(src + (size_t)row * ld + kcol + c4);
            As[c4 + 0][r] = a.x;
            As[c4 + 1][r] = a.y;
            As[c4 + 2][r] = a.z;
            As[c4 + 3][r] = a.w;
        }
        // ---- load B tile: 16 k x 128 cols ----
        {
            #pragma unroll
            for (int i = 0; i < 2; i++) {
                int lin = tid + i * 256;        // 0..511 float4 slots
                int r   = lin >> 5;             // 0..15
                int c4  = (lin & 31) * 4;
                *(float4*)&Bs[r][c4] =
                    *(const float4*)(W + (size_t)(k0 + r) * 128 + c4);
            }
        }
        __syncthreads();

        #pragma unroll
        for (int k = 0; k < BK; k++) {
            float4 a0 = *(const float4*)&As[k][ty * 8];
            float4 a1 = *(const float4*)&As[k][ty * 8 + 4];
            float4 b0 = *(const float4*)&Bs[k][tx * 4];
            float a[8] = {a0.x, a0.y, a0.z, a0.w, a1.x, a1.y, a1.z, a1.w};
            float b[4] = {b0.x, b0.y, b0.z, b0.w};
            #pragma unroll
            for (int i = 0; i < 8; i++)
                #pragma unroll
                for (int j = 0; j < 4; j++)
                    acc[i][j] += a[i] * b[j];
        }
        __syncthreads();
    }

    float bx = 0.f, by = 0.f, bz = 0.f, bw = 0.f;
    if (bias) {
        float4 bb = *(const float4*)(bias + tx * 4);
        bx = bb.x; by = bb.y; bz = bb.z; bw = bb.w;
    }
    #pragma unroll
    for (int i = 0; i < 8; i++) {
        int row = bm + ty * 8 + i;
        if (row < N) {
            float4 o;
            o.x = acc[i][0] + bx;
            o.y = acc[i][1] + by;
            o.z = acc[i][2] + bz;
            o.w = acc[i][3] + bw;
            *(float4*)(Y + (size_t)row * 128 + tx * 4) = o;
        }
    }
}

// ---------------- zero scratch ----------------
__global__ void zero_kernel(float4* __restrict__ p, size_t n4)
{
    size_t i = (size_t)blockIdx.x * blockDim.x + threadIdx.x;
    size_t stride = (size_t)gridDim.x * blockDim.x;
    for (; i < n4; i += stride) p[i] = make_float4(0.f, 0.f, 0.f, 0.f);
}

// ---------------- SpMM: out[row[e],:] += val[e] * ft[col[e],:] ------------
// one warp per edge, 4 floats per lane
__global__ void __launch_bounds__(256) spmm_kernel(
    const int* __restrict__ row, const int* __restrict__ col,
    const float* __restrict__ val, const float* __restrict__ ft,
    float* __restrict__ out, int nE)
{
    int warp = (blockIdx.x * blockDim.x + threadIdx.x) >> 5;
    int lane = threadIdx.x & 31;
    if (warp >= nE) return;
    int r = row[warp];
    int c = col[warp];
    float v = val[warp];
    float4 f = ((const float4*)(ft + (size_t)c * 128))[lane];
    float* o = out + (size_t)r * 128 + lane * 4;
    atomicAdd(o + 0, v * f.x);
    atomicAdd(o + 1, v * f.y);
    atomicAdd(o + 2, v * f.z);
    atomicAdd(o + 3, v * f.w);
}

// ---------------- fold attention weights: u = Wk@watt[:64], v = Wq@watt[64:]
__global__ void prep_uv(const float* __restrict__ wq, const float* __restrict__ wk,
                        const float* __restrict__ watt, float* __restrict__ uv)
{
    int t = threadIdx.x;   // 256 threads
    if (t < 128) {
        float s = 0.f;
        #pragma unroll
        for (int k = 0; k < 64; k++) s += wk[t * 64 + k] * watt[k];
        uv[t] = s;
    } else {
        int j = t - 128;
        float s = 0.f;
        #pragma unroll
        for (int k = 0; k < 64; k++) s += wq[j * 64 + k] * watt[64 + k];
        uv[128 + j] = s;
    }
}

// ---------------- fused attention: elu + softmax(2) + weighted agg --------
__global__ void __launch_bounds__(256) attn_fuse(
    const float* __restrict__ nbb, const float* __restrict__ nbc,
    const float* __restrict__ selfa, const float* __restrict__ uv,
    float* __restrict__ agg, int N)
{
    int warp = (blockIdx.x * blockDim.x + threadIdx.x) >> 5;
    int lane = threadIdx.x & 31;
    if (warp >= N) return;

    float4 b = ((const float4*)(nbb + (size_t)warp * 128))[lane];
    float4 c = ((const float4*)(nbc + (size_t)warp * 128))[lane];
    float4 s = ((const float4*)(selfa + (size_t)warp * 128))[lane];
    float4 u = ((const float4*)uv)[lane];
    float4 v = ((const float4*)(uv + 128))[lane];

    float db = b.x * u.x + b.y * u.y + b.z * u.z + b.w * u.w;
    float dc = c.x * u.x + c.y * u.y + c.z * u.z + c.w * u.w;
    float ds = s.x * v.x + s.y * v.y + s.z * v.z + s.w * v.w;

    #pragma unroll
    for (int o = 16; o; o >>= 1) {
        db += __shfl_xor_sync(0xffffffffu, db, o);
        dc += __shfl_xor_sync(0xffffffffu, dc, o);
        ds += __shfl_xor_sync(0xffffffffu, ds, o);
    }

    float eb = db + ds;
    float ec = dc + ds;
    eb = (eb > 0.f) ? eb : expm1f(eb);    // elu, alpha=1
    ec = (ec > 0.f) ? ec : expm1f(ec);
    float m  = fmaxf(eb, ec);
    float wb = expf(eb - m);
    float wc = expf(ec - m);
    float ab = wb / (wb + wc);
    float ac = 1.f - ab;

    float4 o4;
    o4.x = ab * b.x + ac * c.x;
    o4.y = ab * b.y + ac * c.y;
    o4.z = ab * b.z + ac * c.z;
    o4.w = ab * b.w + ac * c.w;
    ((float4*)(agg + (size_t)warp * 128))[lane] = o4;
}

// ---------------- launcher ----------------
extern "C" void kernel_launch(void* const* d_in, const int* in_sizes, int n_in,
                              void* d_out, int out_size)
{
    const float* x_a       = (const float*)d_in[0];
    const float* x_b       = (const float*)d_in[1];
    const float* x_c       = (const float*)d_in[2];
    const int*   row_ab    = (const int*)d_in[3];
    const int*   col_ab    = (const int*)d_in[4];
    const float* val_ab    = (const float*)d_in[5];
    const int*   row_ac    = (const int*)d_in[6];
    const int*   col_ac    = (const int*)d_in[7];
    const float* val_ac    = (const float*)d_in[8];
    const int*   row_ba    = (const int*)d_in[9];
    const int*   col_ba    = (const int*)d_in[10];
    const float* val_ba    = (const float*)d_in[11];
    const int*   row_ca    = (const int*)d_in[12];
    const int*   col_ca    = (const int*)d_in[13];
    const float* val_ca    = (const float*)d_in[14];
    const float* w_self_a  = (const float*)d_in[15];
    const float* w_self_b  = (const float*)d_in[16];
    const float* w_self_c  = (const float*)d_in[17];
    const float* W_ab      = (const float*)d_in[18];
    const float* W_ac      = (const float*)d_in[19];
    const float* W_ba      = (const float*)d_in[20];
    const float* W_ca      = (const float*)d_in[21];
    const float* bias_a    = (const float*)d_in[22];
    const float* bias_b    = (const float*)d_in[23];
    const float* bias_c    = (const float*)d_in[24];
    const float* w_cat_a   = (const float*)d_in[25];
    const float* w_cat_b   = (const float*)d_in[26];
    const float* w_cat_c   = (const float*)d_in[27];
    const float* w_query_a = (const float*)d_in[28];
    const float* w_keys_a  = (const float*)d_in[29];
    const float* w_att_a   = (const float*)d_in[30];

    float* scratch = nullptr;
    cudaGetSymbolAddress((void**)&scratch, g_scratch);

    float* nbb   = scratch + 0ull  * SZ;
    float* nbc   = scratch + 1ull  * SZ;
    float* aggb  = scratch + 2ull  * SZ;
    float* aggc  = scratch + 3ull  * SZ;
    float* selfa = scratch + 4ull  * SZ;
    float* xbWab = scratch + 5ull  * SZ;
    float* xcWac = scratch + 6ull  * SZ;
    float* xaWba = scratch + 7ull  * SZ;
    float* xaWca = scratch + 8ull  * SZ;
    float* selfb = scratch + 9ull  * SZ;
    float* selfc = scratch + 10ull * SZ;
    float* agga  = scratch + 11ull * SZ;
    float* uv    = scratch + 12ull * SZ;

    float* out   = (float*)d_out;
    float* out_a = out;
    float* out_b = out + (size_t)NA * DOUT;
    float* out_c = out + (size_t)(NA + NB) * DOUT;

    const int GEMM_BLOCKS = (NA + BM - 1) / BM;  // 782 (NA==NB==NC)
    const int SPMM_BLOCKS = (EDG * 32 + 255) / 256;
    const int ATTN_BLOCKS = (NA * 32 + 255) / 256;

    // zero the 4 spmm destinations (contiguous at scratch base)
    zero_kernel<<<8192, 256>>>((float4*)scratch, (size_t)4 * SZ / 4);

    // dense projections
    sgemm_k256<<<GEMM_BLOCKS, 256>>>(x_a, nullptr, w_self_a, nullptr, selfa, NA, 0);
    sgemm_k256<<<GEMM_BLOCKS, 256>>>(x_b, nullptr, W_ab,     nullptr, xbWab, NB, 0);
    sgemm_k256<<<GEMM_BLOCKS, 256>>>(x_c, nullptr, W_ac,     nullptr, xcWac, NC, 0);
    sgemm_k256<<<GEMM_BLOCKS, 256>>>(x_a, nullptr, W_ba,     nullptr, xaWba, NA, 0);
    sgemm_k256<<<GEMM_BLOCKS, 256>>>(x_a, nullptr, W_ca,     nullptr, xaWca, NA, 0);
    sgemm_k256<<<GEMM_BLOCKS, 256>>>(x_b, nullptr, w_self_b, nullptr, selfb, NB, 0);
    sgemm_k256<<<GEMM_BLOCKS, 256>>>(x_c, nullptr, w_self_c, nullptr, selfc, NC, 0);

    // fold attention weights
    prep_uv<<<1, 256>>>(w_query_a, w_keys_a, w_att_a, uv);

    // sparse scatter-adds
    spmm_kernel<<<SPMM_BLOCKS, 256>>>(row_ab, col_ab, val_ab, xbWab, nbb,  EDG);
    spmm_kernel<<<SPMM_BLOCKS, 256>>>(row_ac, col_ac, val_ac, xcWac, nbc,  EDG);
    spmm_kernel<<<SPMM_BLOCKS, 256>>>(row_ba, col_ba, val_ba, xaWba, aggb, EDG);
    spmm_kernel<<<SPMM_BLOCKS, 256>>>(row_ca, col_ca, val_ca, xaWca, aggc, EDG);

    // attention fusion for type 'a'
    attn_fuse<<<ATTN_BLOCKS, 256>>>(nbb, nbc, selfa, uv, agga, NA);

    // final concat GEMMs straight into d_out
    sgemm_k256<<<GEMM_BLOCKS, 256>>>(agga, selfa, w_cat_a, bias_a, out_a, NA, 1);
    sgemm_k256<<<GEMM_BLOCKS, 256>>>(aggb, selfb, w_cat_b, bias_b, out_b, NB, 1);
    sgemm_k256<<<GEMM_BLOCKS, 256>>>(aggc, selfc, w_cat_c, bias_c, out_c, NC, 1);
}

// round 3
// speedup vs baseline: 1.0052x; 1.0052x over previous
#include <cuda_runtime.h>
#include <cstdint>
#include <cstddef>

// ---------------- problem constants ----------------
#define NA 50000
#define NB 50000
#define NC 50000
#define EDG 800000
#define DIN 256
#define DOUT 128
#define SZ (50000 * 128)   // floats per [N,128] buffer

// ---------------- scratch (device global, no runtime alloc) ----------------
// layout (floats):
//  [0]  nbb   (NA*128)   -- spmm dst, must be zeroed
//  [1]  nbc   (NA*128)   -- spmm dst, must be zeroed
//  [2]  aggb  (NB*128)   -- spmm dst, must be zeroed
//  [3]  aggc  (NC*128)   -- spmm dst, must be zeroed
//  [4]  selfa
//  [5]  xbWab
//  [6]  xcWac
//  [7]  xaWba
//  [8]  xaWca
//  [9]  selfb
//  [10] selfc
//  [11] agga
//  then uv[256]
__device__ float g_scratch[12ull * SZ + 256];

// ---------------- SGEMM: Y[N,128] = X[N,256] @ W[256,128] (+bias) ----------
// split==0: X is [N,256] row-major.
// split==1: first 128 K from X ([N,128]), last 128 K from Xb ([N,128]).
#define BM 64
#define BN 128
#define BK 16

__global__ void __launch_bounds__(256) sgemm_k256(
    const float* __restrict__ X, const float* __restrict__ Xb,
    const float* __restrict__ W, const float* __restrict__ bias,
    float* __restrict__ Y, int N, int split)
{
    __shared__ float As[BK][BM + 4];   // pad to keep 16B alignment, reduce conflicts
    __shared__ float Bs[BK][BN];

    const int bm  = blockIdx.x * BM;
    const int tid = threadIdx.x;
    const int tx  = tid & 31;   // 32 groups of 4 output cols
    const int ty  = tid >> 5;   // 8 groups of 8 output rows

    float acc[8][4];
    #pragma unroll
    for (int i = 0; i < 8; i++)
        #pragma unroll
        for (int j = 0; j < 4; j++) acc[i][j] = 0.f;

    for (int k0 = 0; k0 < 256; k0 += BK) {
        // ---- load A tile: 64 rows x 16 k ----
        {
            const float* src;
            int ld, kcol;
            if (!split) { src = X; ld = 256; kcol = k0; }
            else {
                src = (k0 < 128) ? X : Xb;
                ld = 128; kcol = k0 & 127;
            }
            int r  = tid >> 2;          // 0..63
            int c4 = (tid & 3) * 4;     // 0,4,8,12
            int row = bm + r;
            float4 a = make_float4(0.f, 0.f, 0.f, 0.f);
            if (row < N)
                a = *(const float4*)(src + (size_t)row * ld + kcol + c4);
            As[c4 + 0][r] = a.x;
            As[c4 + 1][r] = a.y;
            As[c4 + 2][r] = a.z;
            As[c4 + 3][r] = a.w;
        }
        // ---- load B tile: 16 k x 128 cols ----
        {
            #pragma unroll
            for (int i = 0; i < 2; i++) {
                int lin = tid + i * 256;        // 0..511 float4 slots
                int r   = lin >> 5;             // 0..15
                int c4  = (lin & 31) * 4;
                *(float4*)&Bs[r][c4] =
                    *(const float4*)(W + (size_t)(k0 + r) * 128 + c4);
            }
        }
        __syncthreads();

        #pragma unroll
        for (int k = 0; k < BK; k++) {
            float4 a0 = *(const float4*)&As[k][ty * 8];
            float4 a1 = *(const float4*)&As[k][ty * 8 + 4];
            float4 b0 = *(const float4*)&Bs[k][tx * 4];
            float a[8] = {a0.x, a0.y, a0.z, a0.w, a1.x, a1.y, a1.z, a1.w};
            float b[4] = {b0.x, b0.y, b0.z, b0.w};
            #pragma unroll
            for (int i = 0; i < 8; i++)
                #pragma unroll
                for (int j = 0; j < 4; j++)
                    acc[i][j] += a[i] * b[j];
        }
        __syncthreads();
    }

    float bx = 0.f, by = 0.f, bz = 0.f, bw = 0.f;
    if (bias) {
        float4 bb = *(const float4*)(bias + tx * 4);
        bx = bb.x; by = bb.y; bz = bb.z; bw = bb.w;
    }
    #pragma unroll
    for (int i = 0; i < 8; i++) {
        int row = bm + ty * 8 + i;
        if (row < N) {
            float4 o;
            o.x = acc[i][0] + bx;
            o.y = acc[i][1] + by;
            o.z = acc[i][2] + bz;
            o.w = acc[i][3] + bw;
            *(float4*)(Y + (size_t)row * 128 + tx * 4) = o;
        }
    }
}

// ---------------- zero scratch ----------------
__global__ void zero_kernel(float4* __restrict__ p, size_t n4)
{
    size_t i = (size_t)blockIdx.x * blockDim.x + threadIdx.x;
    size_t stride = (size_t)gridDim.x * blockDim.x;
    for (; i < n4; i += stride) p[i] = make_float4(0.f, 0.f, 0.f, 0.f);
}

// ---------------- SpMM: out[row[e],:] += val[e] * ft[col[e],:] ------------
// one warp per edge, 4 floats per lane
__global__ void __launch_bounds__(256) spmm_kernel(
    const int* __restrict__ row, const int* __restrict__ col,
    const float* __restrict__ val, const float* __restrict__ ft,
    float* __restrict__ out, int nE)
{
    int warp = (blockIdx.x * blockDim.x + threadIdx.x) >> 5;
    int lane = threadIdx.x & 31;
    if (warp >= nE) return;
    int r = row[warp];
    int c = col[warp];
    float v = val[warp];
    float4 f = ((const float4*)(ft + (size_t)c * 128))[lane];
    float* o = out + (size_t)r * 128 + lane * 4;
    atomicAdd(o + 0, v * f.x);
    atomicAdd(o + 1, v * f.y);
    atomicAdd(o + 2, v * f.z);
    atomicAdd(o + 3, v * f.w);
}

// ---------------- fold attention weights: u = Wk@watt[:64], v = Wq@watt[64:]
__global__ void prep_uv(const float* __restrict__ wq, const float* __restrict__ wk,
                        const float* __restrict__ watt, float* __restrict__ uv)
{
    int t = threadIdx.x;   // 256 threads
    if (t < 128) {
        float s = 0.f;
        #pragma unroll
        for (int k = 0; k < 64; k++) s += wk[t * 64 + k] * watt[k];
        uv[t] = s;
    } else {
        int j = t - 128;
        float s = 0.f;
        #pragma unroll
        for (int k = 0; k < 64; k++) s += wq[j * 64 + k] * watt[64 + k];
        uv[128 + j] = s;
    }
}

// ---------------- fused attention: elu + softmax(2) + weighted agg --------
__global__ void __launch_bounds__(256) attn_fuse(
    const float* __restrict__ nbb, const float* __restrict__ nbc,
    const float* __restrict__ selfa, const float* __restrict__ uv,
    float* __restrict__ agg, int N)
{
    int warp = (blockIdx.x * blockDim.x + threadIdx.x) >> 5;
    int lane = threadIdx.x & 31;
    if (warp >= N) return;

    float4 b = ((const float4*)(nbb + (size_t)warp * 128))[lane];
    float4 c = ((const float4*)(nbc + (size_t)warp * 128))[lane];
    float4 s = ((const float4*)(selfa + (size_t)warp * 128))[lane];
    float4 u = ((const float4*)uv)[lane];
    float4 v = ((const float4*)(uv + 128))[lane];

    float db = b.x * u.x + b.y * u.y + b.z * u.z + b.w * u.w;
    float dc = c.x * u.x + c.y * u.y + c.z * u.z + c.w * u.w;
    float ds = s.x * v.x + s.y * v.y + s.z * v.z + s.w * v.w;

    #pragma unroll
    for (int o = 16; o; o >>= 1) {
        db += __shfl_xor_sync(0xffffffffu, db, o);
        dc += __shfl_xor_sync(0xffffffffu, dc, o);
        ds += __shfl_xor_sync(0xffffffffu, ds, o);
    }

    float eb = db + ds;
    float ec = dc + ds;
    eb = (eb > 0.f) ? eb : expm1f(eb);    // elu, alpha=1
    ec = (ec > 0.f) ? ec : expm1f(ec);
    float m  = fmaxf(eb, ec);
    float wb = expf(eb - m);
    float wc = expf(ec - m);
    float ab = wb / (wb + wc);
    float ac = 1.f - ab;

    float4 o4;
    o4.x = ab * b.x + ac * c.x;
    o4.y = ab * b.y + ac * c.y;
    o4.z = ab * b.z + ac * c.z;
    o4.w = ab * b.w + ac * c.w;
    ((float4*)(agg + (size_t)warp * 128))[lane] = o4;
}

// ---------------- launcher ----------------
extern "C" void kernel_launch(void* const* d_in, const int* in_sizes, int n_in,
                              void* d_out, int out_size)
{
    const float* x_a       = (const float*)d_in[0];
    const float* x_b       = (const float*)d_in[1];
    const float* x_c       = (const float*)d_in[2];
    const int*   row_ab    = (const int*)d_in[3];
    const int*   col_ab    = (const int*)d_in[4];
    const float* val_ab    = (const float*)d_in[5];
    const int*   row_ac    = (const int*)d_in[6];
    const int*   col_ac    = (const int*)d_in[7];
    const float* val_ac    = (const float*)d_in[8];
    const int*   row_ba    = (const int*)d_in[9];
    const int*   col_ba    = (const int*)d_in[10];
    const float* val_ba    = (const float*)d_in[11];
    const int*   row_ca    = (const int*)d_in[12];
    const int*   col_ca    = (const int*)d_in[13];
    const float* val_ca    = (const float*)d_in[14];
    const float* w_self_a  = (const float*)d_in[15];
    const float* w_self_b  = (const float*)d_in[16];
    const float* w_self_c  = (const float*)d_in[17];
    const float* W_ab      = (const float*)d_in[18];
    const float* W_ac      = (const float*)d_in[19];
    const float* W_ba      = (const float*)d_in[20];
    const float* W_ca      = (const float*)d_in[21];
    const float* bias_a    = (const float*)d_in[22];
    const float* bias_b    = (const float*)d_in[23];
    const float* bias_c    = (const float*)d_in[24];
    const float* w_cat_a   = (const float*)d_in[25];
    const float* w_cat_b   = (const float*)d_in[26];
    const float* w_cat_c   = (const float*)d_in[27];
    const float* w_query_a = (const float*)d_in[28];
    const float* w_keys_a  = (const float*)d_in[29];
    const float* w_att_a   = (const float*)d_in[30];

    float* scratch = nullptr;
    cudaGetSymbolAddress((void**)&scratch, g_scratch);

    float* nbb   = scratch + 0ull  * SZ;
    float* nbc   = scratch + 1ull  * SZ;
    float* aggb  = scratch + 2ull  * SZ;
    float* aggc  = scratch + 3ull  * SZ;
    float* selfa = scratch + 4ull  * SZ;
    float* xbWab = scratch + 5ull  * SZ;
    float* xcWac = scratch + 6ull  * SZ;
    float* xaWba = scratch + 7ull  * SZ;
    float* xaWca = scratch + 8ull  * SZ;
    float* selfb = scratch + 9ull  * SZ;
    float* selfc = scratch + 10ull * SZ;
    float* agga  = scratch + 11ull * SZ;
    float* uv    = scratch + 12ull * SZ;

    float* out   = (float*)d_out;
    float* out_a = out;
    float* out_b = out + (size_t)NA * DOUT;
    float* out_c = out + (size_t)(NA + NB) * DOUT;

    const int GEMM_BLOCKS = (NA + BM - 1) / BM;  // 782 (NA==NB==NC)
    const int SPMM_BLOCKS = (EDG * 32 + 255) / 256;
    const int ATTN_BLOCKS = (NA * 32 + 255) / 256;

    // zero the 4 spmm destinations (contiguous at scratch base)
    zero_kernel<<<8192, 256>>>((float4*)scratch, (size_t)4 * SZ / 4);

    // dense projections
    sgemm_k256<<<GEMM_BLOCKS, 256>>>(x_a, nullptr, w_self_a, nullptr, selfa, NA, 0);
    sgemm_k256<<<GEMM_BLOCKS, 256>>>(x_b, nullptr, W_ab,     nullptr, xbWab, NB, 0);
    sgemm_k256<<<GEMM_BLOCKS, 256>>>(x_c, nullptr, W_ac,     nullptr, xcWac, NC, 0);
    sgemm_k256<<<GEMM_BLOCKS, 256>>>(x_a, nullptr, W_ba,     nullptr, xaWba, NA, 0);
    sgemm_k256<<<GEMM_BLOCKS, 256>>>(x_a, nullptr, W_ca,     nullptr, xaWca, NA, 0);
    sgemm_k256<<<GEMM_BLOCKS, 256>>>(x_b, nullptr, w_self_b, nullptr, selfb, NB, 0);
    sgemm_k256<<<GEMM_BLOCKS, 256>>>(x_c, nullptr, w_self_c, nullptr, selfc, NC, 0);

    // fold attention weights
    prep_uv<<<1, 256>>>(w_query_a, w_keys_a, w_att_a, uv);

    // sparse scatter-adds
    spmm_kernel<<<SPMM_BLOCKS, 256>>>(row_ab, col_ab, val_ab, xbWab, nbb,  EDG);
    spmm_kernel<<<SPMM_BLOCKS, 256>>>(row_ac, col_ac, val_ac, xcWac, nbc,  EDG);
    spmm_kernel<<<SPMM_BLOCKS, 256>>>(row_ba, col_ba, val_ba, xaWba, aggb, EDG);
    spmm_kernel<<<SPMM_BLOCKS, 256>>>(row_ca, col_ca, val_ca, xaWca, aggc, EDG);

    // attention fusion for type 'a'
    attn_fuse<<<ATTN_BLOCKS, 256>>>(nbb, nbc, selfa, uv, agga, NA);

    // final concat GEMMs straight into d_out
    sgemm_k256<<<GEMM_BLOCKS, 256>>>(agga, selfa, w_cat_a, bias_a, out_a, NA, 1);
    sgemm_k256<<<GEMM_BLOCKS, 256>>>(aggb, selfb, w_cat_b, bias_b, out_b, NB, 1);
    sgemm_k256<<<GEMM_BLOCKS, 256>>>(aggc, selfc, w_cat_c, bias_c, out_c, NC, 1);
}

// round 4
// speedup vs baseline: 2.0188x; 2.0084x over previous
#include <cuda_runtime.h>
#include <cstdint>
#include <cstddef>

// ---------------- problem constants ----------------
#define NA 50000
#define NB 50000
#define NC 50000
#define EDG 800000
#define DIN 256
#define DOUT 128
#define SZ (50000 * 128)   // floats per [N,128] buffer

// scratch layout (floats):
//  slots 0-3: nbb, nbc, aggb, aggc  (spmm dst, zeroed)
//  slots 4-7: xbWab, xcWac, xaWba, xaWca
//  slot  8  : agga
//  then transposed tf32 weights + uv/wv
#define W_OFF   (9ull * SZ)
#define OFF_WabT   (W_OFF)
#define OFF_WacT   (OFF_WabT + 256*128)
#define OFF_WbaT   (OFF_WacT + 256*128)
#define OFF_WcaT   (OFF_WbaT + 256*128)
#define OFF_WC1A   (OFF_WcaT + 256*128)
#define OFF_WC1B   (OFF_WC1A + 128*128)
#define OFF_WC1C   (OFF_WC1B + 128*128)
#define OFF_WFA    (OFF_WC1C + 128*128)
#define OFF_WFB    (OFF_WFA  + 256*128)
#define OFF_WFC    (OFF_WFB  + 256*128)
#define OFF_UV     (OFF_WFC  + 256*128)
#define SCRATCH_TOTAL (OFF_UV + 512)

__device__ float g_scratch[SCRATCH_TOTAL];

// ---------------- helpers ----------------
__device__ __forceinline__ unsigned f2tf(float x) {
    unsigned u; asm("cvt.rna.tf32.f32 %0, %1;" : "=r"(u) : "f"(x)); return u;
}

__device__ __forceinline__ void ldsm4(unsigned &r0, unsigned &r1, unsigned &r2,
                                      unsigned &r3, unsigned addr) {
    asm volatile("ldmatrix.sync.aligned.m8n8.x4.shared.b16 {%0,%1,%2,%3}, [%4];"
                 : "=r"(r0), "=r"(r1), "=r"(r2), "=r"(r3) : "r"(addr));
}

__device__ __forceinline__ void mma_tf32(float c[4], const unsigned a[4],
                                         unsigned b0, unsigned b1) {
    asm volatile(
        "mma.sync.aligned.m16n8k8.row.col.f32.tf32.tf32.f32 "
        "{%0,%1,%2,%3}, {%4,%5,%6,%7}, {%8,%9}, {%0,%1,%2,%3};"
        : "+f"(c[0]), "+f"(c[1]), "+f"(c[2]), "+f"(c[3])
        : "r"(a[0]), "r"(a[1]), "r"(a[2]), "r"(a[3]), "r"(b0), "r"(b1));
}

// ---------------- tf32 tensor-core GEMM ----------------
// Y[N,128] = concat-K( A0 [,A1] ) @ concat-K( B0T [,B1T] )  (+bias)
// A row-major fp32. B*T: tf32 bits, transposed [n=128][K] row-major.
// Split at k=128 when A1/B1T non-null.
__global__ void __launch_bounds__(256, 2) gemm_tf32(
    const float* __restrict__ A0, int lda0,
    const float* __restrict__ A1, int lda1,
    const unsigned* __restrict__ B0T, int ldb0,
    const unsigned* __restrict__ B1T, int ldb1,
    const float* __restrict__ bias,
    float* __restrict__ Y, int N, int K)
{
    __shared__ unsigned As[128][36];
    __shared__ unsigned Bs[128][36];

    const int tid  = threadIdx.x;
    const int lane = tid & 31;
    const int w    = tid >> 5;
    const int bm   = blockIdx.x * 128;

    const int wm = (w >> 2) * 64;   // 2 warp-rows of 64
    const int wn = (w & 3) * 32;    // 4 warp-cols of 32

    // ldmatrix per-thread sub-tile offsets
    const int a_mo = ((lane >> 3) & 1) * 8 + (lane & 7);
    const int a_ko = (lane >> 4) * 4;
    const int b_no = (lane >> 4) * 8 + (lane & 7);
    const int b_ko = ((lane >> 3) & 1) * 4;

    // staging coords
    const int am  = tid >> 1;          // 0..127 (m row)
    const int akb = (tid & 1) * 16;    // 0/16
    const int bn  = tid & 127;         // B row (n)
    const int bkh = (tid >> 7) * 16;   // 0/16

    float acc[4][4][4];
    #pragma unroll
    for (int i = 0; i < 4; i++)
        #pragma unroll
        for (int j = 0; j < 4; j++)
            #pragma unroll
            for (int c = 0; c < 4; c++) acc[i][j][c] = 0.f;

    const int arow = bm + am;

    for (int k0 = 0; k0 < K; k0 += 32) {
        __syncthreads();
        // ---- stage A (fp32 -> tf32) ----
        {
            const float* src; int ld, col;
            if (A1 && k0 >= 128) { src = A1; ld = lda1; col = k0 - 128; }
            else                 { src = A0; ld = lda0; col = k0; }
            #pragma unroll
            for (int c = 0; c < 4; c++) {
                float4 v = make_float4(0.f, 0.f, 0.f, 0.f);
                if (arow < N)
                    v = *(const float4*)(src + (size_t)arow * ld + col + akb + c * 4);
                uint4 t;
                t.x = f2tf(v.x); t.y = f2tf(v.y); t.z = f2tf(v.z); t.w = f2tf(v.w);
                *(uint4*)&As[am][akb + c * 4] = t;
            }
        }
        // ---- stage B (already tf32, transposed) ----
        {
            const unsigned* src;
            if (B1T && k0 >= 128) src = B1T + (size_t)bn * ldb1 + (k0 - 128) + bkh;
            else                  src = B0T + (size_t)bn * ldb0 + k0 + bkh;
            #pragma unroll
            for (int c = 0; c < 4; c++)
                *(uint4*)&Bs[bn][bkh + c * 4] = *(const uint4*)(src + c * 4);
        }
        __syncthreads();
        // ---- compute: 4 x k8 steps ----
        #pragma unroll
        for (int ks = 0; ks < 4; ks++) {
            const int k8 = ks * 8;
            unsigned a[4][4], b0[4], b1[4];
            #pragma unroll
            for (int mt = 0; mt < 4; mt++) {
                unsigned addr = (unsigned)__cvta_generic_to_shared(
                    &As[wm + mt * 16 + a_mo][k8 + a_ko]);
                ldsm4(a[mt][0], a[mt][1], a[mt][2], a[mt][3], addr);
            }
            #pragma unroll
            for (int np = 0; np < 2; np++) {
                unsigned addr = (unsigned)__cvta_generic_to_shared(
                    &Bs[wn + np * 16 + b_no][k8 + b_ko]);
                ldsm4(b0[np * 2], b1[np * 2], b0[np * 2 + 1], b1[np * 2 + 1], addr);
            }
            #pragma unroll
            for (int mt = 0; mt < 4; mt++)
                #pragma unroll
                for (int nt = 0; nt < 4; nt++)
                    mma_tf32(acc[mt][nt], a[mt], b0[nt], b1[nt]);
        }
    }

    // ---- epilogue ----
    const int g = lane >> 2, tg = lane & 3;
    #pragma unroll
    for (int nt = 0; nt < 4; nt++) {
        int cc = wn + nt * 8 + tg * 2;
        float bx = bias ? bias[cc]     : 0.f;
        float by = bias ? bias[cc + 1] : 0.f;
        #pragma unroll
        for (int mt = 0; mt < 4; mt++) {
            int r = bm + wm + mt * 16 + g;
            if (r < N) {
                float2 o = make_float2(acc[mt][nt][0] + bx, acc[mt][nt][1] + by);
                *(float2*)(Y + (size_t)r * 128 + cc) = o;
            }
            if (r + 8 < N) {
                float2 o = make_float2(acc[mt][nt][2] + bx, acc[mt][nt][3] + by);
                *(float2*)(Y + (size_t)(r + 8) * 128 + cc) = o;
            }
        }
    }
}

// ---------------- weight prep: transpose [K,128] -> tf32 [128][K] ----------
__global__ void transpose_tf32(const float* __restrict__ in,
                               unsigned* __restrict__ out, int K)
{
    int idx = blockIdx.x * blockDim.x + threadIdx.x;
    if (idx >= K * 128) return;
    int k = idx >> 7, n = idx & 127;
    out[(size_t)n * K + k] = f2tf(in[(size_t)k * 128 + n]);
}

// Wfold[k,n] = sum_j w_self[k,j] * w_cat[128+j, n];  write transposed tf32 [128][256]
__global__ void fold_wcat(const float* __restrict__ wself,
                          const float* __restrict__ wcat,
                          unsigned* __restrict__ outT)
{
    int idx = blockIdx.x * blockDim.x + threadIdx.x;   // 256*128
    int k = idx >> 7, n = idx & 127;
    const float* w2 = wcat + 128 * 128;
    float s = 0.f;
    #pragma unroll 8
    for (int j = 0; j < 128; j++) s += wself[k * 128 + j] * w2[j * 128 + n];
    outT[(size_t)n * 256 + k] = f2tf(s);
}

// u = w_keys @ w_att[:64]  (128),  v = w_query @ w_att[64:]  (128)
__global__ void prep_uv(const float* __restrict__ wq, const float* __restrict__ wk,
                        const float* __restrict__ watt, float* __restrict__ uv)
{
    int t = threadIdx.x;   // 256
    if (t < 128) {
        float s = 0.f;
        #pragma unroll
        for (int j = 0; j < 64; j++) s += wk[t * 64 + j] * watt[j];
        uv[t] = s;
    } else {
        int i = t - 128;
        float s = 0.f;
        #pragma unroll
        for (int j = 0; j < 64; j++) s += wq[i * 64 + j] * watt[64 + j];
        uv[128 + i] = s;
    }
}

// wv = w_self_a @ v  (256)
__global__ void prep_wv(const float* __restrict__ wself_a,
                        const float* __restrict__ uv)
{
    int k = threadIdx.x;   // 256
    const float* v = uv + 128;
    float s = 0.f;
    #pragma unroll 8
    for (int j = 0; j < 128; j++) s += wself_a[k * 128 + j] * v[j];
    float* wv = (float*)uv + 256;
    wv[k] = s;
}

// ---------------- zero scratch ----------------
__global__ void zero_kernel(float4* __restrict__ p, size_t n4)
{
    size_t i = (size_t)blockIdx.x * blockDim.x + threadIdx.x;
    size_t stride = (size_t)gridDim.x * blockDim.x;
    for (; i < n4; i += stride) p[i] = make_float4(0.f, 0.f, 0.f, 0.f);
}

// ---------------- SpMM: out[row[e],:] += val[e] * ft[col[e],:] ------------
// one warp per edge, one red.v4 per lane
__global__ void __launch_bounds__(256) spmm_kernel(
    const int* __restrict__ row, const int* __restrict__ col,
    const float* __restrict__ val, const float* __restrict__ ft,
    float* __restrict__ out, int nE)
{
    int warp = (blockIdx.x * blockDim.x + threadIdx.x) >> 5;
    int lane = threadIdx.x & 31;
    if (warp >= nE) return;
    int r = row[warp];
    int c = col[warp];
    float v = val[warp];
    float4 f = ((const float4*)(ft + (size_t)c * 128))[lane];
    float* o = out + (size_t)r * 128 + lane * 4;
    asm volatile("red.global.add.v4.f32 [%0], {%1,%2,%3,%4};"
                 :: "l"(o), "f"(v * f.x), "f"(v * f.y), "f"(v * f.z), "f"(v * f.w)
                 : "memory");
}

// ---------------- fused attention: elu + softmax(2) + weighted agg --------
__global__ void __launch_bounds__(256) attn_fuse(
    const float* __restrict__ nbb, const float* __restrict__ nbc,
    const float* __restrict__ xa, const float* __restrict__ uv,
    float* __restrict__ agg, int N)
{
    int warp = (blockIdx.x * blockDim.x + threadIdx.x) >> 5;
    int lane = threadIdx.x & 31;
    if (warp >= N) return;

    float4 b  = ((const float4*)(nbb + (size_t)warp * 128))[lane];
    float4 c  = ((const float4*)(nbc + (size_t)warp * 128))[lane];
    float4 u4 = ((const float4*)uv)[lane];
    float4 x0 = ((const float4*)(xa + (size_t)warp * 256))[lane];
    float4 x1 = ((const float4*)(xa + (size_t)warp * 256))[lane + 32];
    float4 w0 = ((const float4*)(uv + 256))[lane];
    float4 w1 = ((const float4*)(uv + 256))[lane + 32];

    float db = b.x * u4.x + b.y * u4.y + b.z * u4.z + b.w * u4.w;
    float dc = c.x * u4.x + c.y * u4.y + c.z * u4.z + c.w * u4.w;
    float ds = x0.x * w0.x + x0.y * w0.y + x0.z * w0.z + x0.w * w0.w
             + x1.x * w1.x + x1.y * w1.y + x1.z * w1.z + x1.w * w1.w;

    #pragma unroll
    for (int o = 16; o; o >>= 1) {
        db += __shfl_xor_sync(0xffffffffu, db, o);
        dc += __shfl_xor_sync(0xffffffffu, dc, o);
        ds += __shfl_xor_sync(0xffffffffu, ds, o);
    }

    float eb = db + ds;
    float ec = dc + ds;
    eb = (eb > 0.f) ? eb : expm1f(eb);    // elu, alpha=1
    ec = (ec > 0.f) ? ec : expm1f(ec);
    float m  = fmaxf(eb, ec);
    float wb = expf(eb - m);
    float wc = expf(ec - m);
    float ab = wb / (wb + wc);
    float ac = 1.f - ab;

    float4 o4;
    o4.x = ab * b.x + ac * c.x;
    o4.y = ab * b.y + ac * c.y;
    o4.z = ab * b.z + ac * c.z;
    o4.w = ab * b.w + ac * c.w;
    ((float4*)(agg + (size_t)warp * 128))[lane] = o4;
}

// ---------------- launcher ----------------
extern "C" void kernel_launch(void* const* d_in, const int* in_sizes, int n_in,
                              void* d_out, int out_size)
{
    const float* x_a       = (const float*)d_in[0];
    const float* x_b       = (const float*)d_in[1];
    const float* x_c       = (const float*)d_in[2];
    const int*   row_ab    = (const int*)d_in[3];
    const int*   col_ab    = (const int*)d_in[4];
    const float* val_ab    = (const float*)d_in[5];
    const int*   row_ac    = (const int*)d_in[6];
    const int*   col_ac    = (const int*)d_in[7];
    const float* val_ac    = (const float*)d_in[8];
    const int*   row_ba    = (const int*)d_in[9];
    const int*   col_ba    = (const int*)d_in[10];
    const float* val_ba    = (const float*)d_in[11];
    const int*   row_ca    = (const int*)d_in[12];
    const int*   col_ca    = (const int*)d_in[13];
    const float* val_ca    = (const float*)d_in[14];
    const float* w_self_a  = (const float*)d_in[15];
    const float* w_self_b  = (const float*)d_in[16];
    const float* w_self_c  = (const float*)d_in[17];
    const float* W_ab      = (const float*)d_in[18];
    const float* W_ac      = (const float*)d_in[19];
    const float* W_ba      = (const float*)d_in[20];
    const float* W_ca      = (const float*)d_in[21];
    const float* bias_a    = (const float*)d_in[22];
    const float* bias_b    = (const float*)d_in[23];
    const float* bias_c    = (const float*)d_in[24];
    const float* w_cat_a   = (const float*)d_in[25];
    const float* w_cat_b   = (const float*)d_in[26];
    const float* w_cat_c   = (const float*)d_in[27];
    const float* w_query_a = (const float*)d_in[28];
    const float* w_keys_a  = (const float*)d_in[29];
    const float* w_att_a   = (const float*)d_in[30];

    float* scratch = nullptr;
    cudaGetSymbolAddress((void**)&scratch, g_scratch);

    float* nbb   = scratch + 0ull * SZ;
    float* nbc   = scratch + 1ull * SZ;
    float* aggb  = scratch + 2ull * SZ;
    float* aggc  = scratch + 3ull * SZ;
    float* xbWab = scratch + 4ull * SZ;
    float* xcWac = scratch + 5ull * SZ;
    float* xaWba = scratch + 6ull * SZ;
    float* xaWca = scratch + 7ull * SZ;
    float* agga  = scratch + 8ull * SZ;

    unsigned* WabT = (unsigned*)(scratch + OFF_WabT);
    unsigned* WacT = (unsigned*)(scratch + OFF_WacT);
    unsigned* WbaT = (unsigned*)(scratch + OFF_WbaT);
    unsigned* WcaT = (unsigned*)(scratch + OFF_WcaT);
    unsigned* Wc1aT = (unsigned*)(scratch + OFF_WC1A);
    unsigned* Wc1bT = (unsigned*)(scratch + OFF_WC1B);
    unsigned* Wc1cT = (unsigned*)(scratch + OFF_WC1C);
    unsigned* WfaT  = (unsigned*)(scratch + OFF_WFA);
    unsigned* WfbT  = (unsigned*)(scratch + OFF_WFB);
    unsigned* WfcT  = (unsigned*)(scratch + OFF_WFC);
    float*    uv    = scratch + OFF_UV;

    float* out   = (float*)d_out;
    float* out_a = out;
    float* out_b = out + (size_t)NA * DOUT;
    float* out_c = out + (size_t)(NA + NB) * DOUT;

    const int GB  = (NA + 127) / 128;                 // 391
    const int SPB = (EDG * 32 + 255) / 256;           // 100000
    const int ATB = (NA * 32 + 255) / 256;            // 6250

    // ---- tiny weight prep ----
    prep_uv<<<1, 256>>>(w_query_a, w_keys_a, w_att_a, uv);
    prep_wv<<<1, 256>>>(w_self_a, uv);
    transpose_tf32<<<128, 256>>>(W_ab, WabT, 256);
    transpose_tf32<<<128, 256>>>(W_ac, WacT, 256);
    transpose_tf32<<<128, 256>>>(W_ba, WbaT, 256);
    transpose_tf32<<<128, 256>>>(W_ca, WcaT, 256);
    transpose_tf32<<<64, 256>>>(w_cat_a, Wc1aT, 128);   // rows 0..127 of w_cat
    transpose_tf32<<<64, 256>>>(w_cat_b, Wc1bT, 128);
    transpose_tf32<<<64, 256>>>(w_cat_c, Wc1cT, 128);
    fold_wcat<<<128, 256>>>(w_self_a, w_cat_a, WfaT);
    fold_wcat<<<128, 256>>>(w_self_b, w_cat_b, WfbT);
    fold_wcat<<<128, 256>>>(w_self_c, w_cat_c, WfcT);

    // ---- zero spmm destinations (slots 0-3 contiguous) ----
    zero_kernel<<<8192, 256>>>((float4*)scratch, (size_t)4 * SZ / 4);

    // ---- projection GEMMs (tf32 tensor core) ----
    gemm_tf32<<<GB, 256>>>(x_b, 256, nullptr, 0, WabT, 256, nullptr, 0, nullptr, xbWab, NB, 256);
    gemm_tf32<<<GB, 256>>>(x_c, 256, nullptr, 0, WacT, 256, nullptr, 0, nullptr, xcWac, NC, 256);
    gemm_tf32<<<GB, 256>>>(x_a, 256, nullptr, 0, WbaT, 256, nullptr, 0, nullptr, xaWba, NA, 256);
    gemm_tf32<<<GB, 256>>>(x_a, 256, nullptr, 0, WcaT, 256, nullptr, 0, nullptr, xaWca, NA, 256);

    // ---- sparse scatter-adds (vector red) ----
    spmm_kernel<<<SPB, 256>>>(row_ab, col_ab, val_ab, xbWab, nbb,  EDG);
    spmm_kernel<<<SPB, 256>>>(row_ac, col_ac, val_ac, xcWac, nbc,  EDG);
    spmm_kernel<<<SPB, 256>>>(row_ba, col_ba, val_ba, xaWba, aggb, EDG);
    spmm_kernel<<<SPB, 256>>>(row_ca, col_ca, val_ca, xaWca, aggc, EDG);

    // ---- attention fusion for type 'a' (self_a never materialized) ----
    attn_fuse<<<ATB, 256>>>(nbb, nbc, x_a, uv, agga, NA);

    // ---- output GEMMs: [agg | x] @ [wcat1 ; Wfold] + bias, K=384 ----
    gemm_tf32<<<GB, 256>>>(agga, 128, x_a, 256, Wc1aT, 128, WfaT, 256, bias_a, out_a, NA, 384);
    gemm_tf32<<<GB, 256>>>(aggb, 128, x_b, 256, Wc1bT, 128, WfbT, 256, bias_b, out_b, NB, 384);
    gemm_tf32<<<GB, 256>>>(aggc, 128, x_c, 256, Wc1cT, 128, WfcT, 256, bias_c, out_c, NC, 384);
}

// round 5
// speedup vs baseline: 3.1288x; 1.5498x over previous
#include <cuda_runtime.h>
#include <cstdint>
#include <cstddef>

// ---------------- problem constants ----------------
#define NA 50000
#define NB 50000
#define NC 50000
#define NROW 50000
#define EDG 800000
#define DIN 256
#define DOUT 128
#define SZ (50000 * 128)   // floats per [N,128] buffer

// scratch layout (floats):
//  slots 0-3: nbb, nbc, aggb, aggc   (spmm gather outputs)
//  slots 4-7: xbWab, xcWac, xaWba, xaWca
//  slot  8  : agga
//  then tf32 weights, uv, CSR arrays
#define W_OFF      (9ull * SZ)
#define OFF_WabT   (W_OFF)
#define OFF_WacT   (OFF_WabT + 256*128)
#define OFF_WbaT   (OFF_WacT + 256*128)
#define OFF_WcaT   (OFF_WbaT + 256*128)
#define OFF_WC1A   (OFF_WcaT + 256*128)
#define OFF_WC1B   (OFF_WC1A + 128*128)
#define OFF_WC1C   (OFF_WC1B + 128*128)
#define OFF_WFA    (OFF_WC1C + 128*128)
#define OFF_WFB    (OFF_WFA  + 256*128)
#define OFF_WFC    (OFF_WFB  + 256*128)
#define OFF_UV     (OFF_WFC  + 256*128)
#define OFF_DEG    (OFF_UV   + 512)              // 4 * 50000 ints
#define OFF_BASE   (OFF_DEG  + 4*50000)          // 4 * 50001 ints
#define OFF_CUR    (OFF_BASE + 4*50004)          // 4 * 50000 ints
#define OFF_EPACK  (((OFF_CUR + 4*50000) + 1) & ~1ull)  // 4 * 800000 int2 (8B aligned)
#define SCRATCH_TOTAL (OFF_EPACK + 4ull*EDG*2)

__device__ float g_scratch[SCRATCH_TOTAL];

// ---------------- helpers ----------------
__device__ __forceinline__ unsigned f2tf(float x) {
    unsigned u; asm("cvt.rna.tf32.f32 %0, %1;" : "=r"(u) : "f"(x)); return u;
}

__device__ __forceinline__ void ldsm4(unsigned &r0, unsigned &r1, unsigned &r2,
                                      unsigned &r3, unsigned addr) {
    asm volatile("ldmatrix.sync.aligned.m8n8.x4.shared.b16 {%0,%1,%2,%3}, [%4];"
                 : "=r"(r0), "=r"(r1), "=r"(r2), "=r"(r3) : "r"(addr));
}

__device__ __forceinline__ void mma_tf32(float c[4], const unsigned a[4],
                                         unsigned b0, unsigned b1) {
    asm volatile(
        "mma.sync.aligned.m16n8k8.row.col.f32.tf32.tf32.f32 "
        "{%0,%1,%2,%3}, {%4,%5,%6,%7}, {%8,%9}, {%0,%1,%2,%3};"
        : "+f"(c[0]), "+f"(c[1]), "+f"(c[2]), "+f"(c[3])
        : "r"(a[0]), "r"(a[1]), "r"(a[2]), "r"(a[3]), "r"(b0), "r"(b1));
}

__device__ __forceinline__ void cpasync16(void* sdst, const void* gsrc, int nbytes) {
    unsigned s = (unsigned)__cvta_generic_to_shared(sdst);
    asm volatile("cp.async.cg.shared.global [%0], [%1], 16, %2;\n"
                 :: "r"(s), "l"(gsrc), "r"(nbytes));
}

// ---------------- tf32 tensor-core GEMM, cp.async 2-stage ----------------
// Y[N,128] = concat-K( A0 [,A1] ) @ concat-K( B0T [,B1T] )  (+bias)
// A row-major fp32. B*T: tf32 bits, transposed [128][K] row-major.
// K split at 128 when A1/B1T non-null.
__global__ void __launch_bounds__(256, 2) gemm_tf32(
    const float* __restrict__ A0, int lda0,
    const float* __restrict__ A1, int lda1,
    const unsigned* __restrict__ B0T, int ldb0,
    const unsigned* __restrict__ B1T, int ldb1,
    const float* __restrict__ bias,
    float* __restrict__ Y, int N, int K)
{
    __shared__ float    As[2][128][20];   // 16 k + 4 pad
    __shared__ unsigned Bs[2][128][20];

    const int tid  = threadIdx.x;
    const int lane = tid & 31;
    const int w    = tid >> 5;
    const int bm   = blockIdx.x * 128;

    const int wm = (w >> 2) * 64;   // 2 warp-rows of 64
    const int wn = (w & 3) * 32;    // 4 warp-cols of 32

    const int a_mo = ((lane >> 3) & 1) * 8 + (lane & 7);
    const int a_ko = (lane >> 4) * 4;
    const int b_no = (lane >> 4) * 8 + (lane & 7);
    const int b_ko = ((lane >> 3) & 1) * 4;

    float acc[4][4][4];
    #pragma unroll
    for (int i = 0; i < 4; i++)
        #pragma unroll
        for (int j = 0; j < 4; j++)
            #pragma unroll
            for (int c = 0; c < 4; c++) acc[i][j][c] = 0.f;

    const int NK = K >> 4;

    auto stage = [&](int buf, int k0) {
        // A tile: 128 rows x 16 floats, 512 16B chunks, 2/thread
        const float* asrc; int ld, colb;
        if (A1 && k0 >= 128) { asrc = A1; ld = lda1; colb = k0 - 128; }
        else                 { asrc = A0; ld = lda0; colb = k0; }
        #pragma unroll
        for (int i = 0; i < 2; i++) {
            int slot = tid + i * 256;
            int r = slot >> 2, c = (slot & 3) * 4;
            int grow = bm + r;
            const float* src = asrc + (size_t)(grow < N ? grow : 0) * ld + colb + c;
            cpasync16(&As[buf][r][c], src, grow < N ? 16 : 0);
        }
        // B tile: 128 n-rows x 16 tf32
        const unsigned* bsrc; int ldb;
        if (B1T && k0 >= 128) { bsrc = B1T + (k0 - 128); ldb = ldb1; }
        else                  { bsrc = B0T + k0;         ldb = ldb0; }
        #pragma unroll
        for (int i = 0; i < 2; i++) {
            int slot = tid + i * 256;
            int n = slot >> 2, c = (slot & 3) * 4;
            cpasync16(&Bs[buf][n][c], bsrc + (size_t)n * ldb + c, 16);
        }
        asm volatile("cp.async.commit_group;\n" ::);
    };

    stage(0, 0);

    for (int kt = 0; kt < NK; kt++) {
        if (kt + 1 < NK) {
            stage((kt + 1) & 1, (kt + 1) * 16);
            asm volatile("cp.async.wait_group 1;\n" ::);
        } else {
            asm volatile("cp.async.wait_group 0;\n" ::);
        }
        __syncthreads();

        const int buf = kt & 1;
        #pragma unroll
        for (int ks = 0; ks < 2; ks++) {
            const int k8 = ks * 8;
            unsigned a[4][4], b0[4], b1[4];
            #pragma unroll
            for (int mt = 0; mt < 4; mt++) {
                unsigned addr = (unsigned)__cvta_generic_to_shared(
                    &As[buf][wm + mt * 16 + a_mo][k8 + a_ko]);
                ldsm4(a[mt][0], a[mt][1], a[mt][2], a[mt][3], addr);
                #pragma unroll
                for (int r = 0; r < 4; r++)
                    a[mt][r] = f2tf(__uint_as_float(a[mt][r]));
            }
            #pragma unroll
            for (int np = 0; np < 2; np++) {
                unsigned addr = (unsigned)__cvta_generic_to_shared(
                    &Bs[buf][wn + np * 16 + b_no][k8 + b_ko]);
                ldsm4(b0[np * 2], b1[np * 2], b0[np * 2 + 1], b1[np * 2 + 1], addr);
            }
            #pragma unroll
            for (int mt = 0; mt < 4; mt++)
                #pragma unroll
                for (int nt = 0; nt < 4; nt++)
                    mma_tf32(acc[mt][nt], a[mt], b0[nt], b1[nt]);
        }
        __syncthreads();
    }

    // ---- epilogue ----
    const int g = lane >> 2, tg = lane & 3;
    #pragma unroll
    for (int nt = 0; nt < 4; nt++) {
        int cc = wn + nt * 8 + tg * 2;
        float bx = bias ? bias[cc]     : 0.f;
        float by = bias ? bias[cc + 1] : 0.f;
        #pragma unroll
        for (int mt = 0; mt < 4; mt++) {
            int r = bm + wm + mt * 16 + g;
            if (r < N) {
                float2 o = make_float2(acc[mt][nt][0] + bx, acc[mt][nt][1] + by);
                *(float2*)(Y + (size_t)r * 128 + cc) = o;
            }
            if (r + 8 < N) {
                float2 o = make_float2(acc[mt][nt][2] + bx, acc[mt][nt][3] + by);
                *(float2*)(Y + (size_t)(r + 8) * 128 + cc) = o;
            }
        }
    }
}

// ---------------- weight prep (batched over relations via blockIdx.y) -----
// transpose [256,128] -> tf32 [128][256], 4 matrices
__global__ void transpose256_4(const float* __restrict__ w0, const float* __restrict__ w1,
                               const float* __restrict__ w2, const float* __restrict__ w3,
                               unsigned* __restrict__ outbase)
{
    const float* in = (blockIdx.y == 0) ? w0 : (blockIdx.y == 1) ? w1
                    : (blockIdx.y == 2) ? w2 : w3;
    unsigned* out = outbase + (size_t)blockIdx.y * 256 * 128;
    int idx = blockIdx.x * blockDim.x + threadIdx.x;   // 0..32767
    if (idx >= 256 * 128) return;
    int k = idx >> 7, n = idx & 127;
    out[(size_t)n * 256 + k] = f2tf(in[(size_t)k * 128 + n]);
}

// transpose rows 0..127 of w_cat [256,128] -> tf32 [128][128], 3 matrices
__global__ void transpose128_3(const float* __restrict__ w0, const float* __restrict__ w1,
                               const float* __restrict__ w2, unsigned* __restrict__ outbase)
{
    const float* in = (blockIdx.y == 0) ? w0 : (blockIdx.y == 1) ? w1 : w2;
    unsigned* out = outbase + (size_t)blockIdx.y * 128 * 128;
    int idx = blockIdx.x * blockDim.x + threadIdx.x;
    if (idx >= 128 * 128) return;
    int k = idx >> 7, n = idx & 127;
    out[(size_t)n * 128 + k] = f2tf(in[(size_t)k * 128 + n]);
}

// Wfold[k,n] = sum_j w_self[k,j] * w_cat[128+j, n]; write transposed tf32 [128][256]
__global__ void fold3(const float* __restrict__ ws0, const float* __restrict__ ws1,
                      const float* __restrict__ ws2,
                      const float* __restrict__ wc0, const float* __restrict__ wc1,
                      const float* __restrict__ wc2, unsigned* __restrict__ outbase)
{
    const float* wself = (blockIdx.y == 0) ? ws0 : (blockIdx.y == 1) ? ws1 : ws2;
    const float* wcat  = (blockIdx.y == 0) ? wc0 : (blockIdx.y == 1) ? wc1 : wc2;
    unsigned* outT = outbase + (size_t)blockIdx.y * 256 * 128;
    int idx = blockIdx.x * blockDim.x + threadIdx.x;
    if (idx >= 256 * 128) return;
    int k = idx >> 7, n = idx & 127;
    const float* w2 = wcat + 128 * 128;
    float s = 0.f;
    #pragma unroll 8
    for (int j = 0; j < 128; j++) s += wself[k * 128 + j] * w2[j * 128 + n];
    outT[(size_t)n * 256 + k] = f2tf(s);
}

// u = w_keys @ w_att[:64], v = w_query @ w_att[64:], wv = w_self_a @ v
__global__ void prep_uv(const float* __restrict__ wq, const float* __restrict__ wk,
                        const float* __restrict__ watt, float* __restrict__ uv)
{
    int t = threadIdx.x;   // 256
    if (t < 128) {
        float s = 0.f;
        #pragma unroll
        for (int j = 0; j < 64; j++) s += wk[t * 64 + j] * watt[j];
        uv[t] = s;
    } else {
        int i = t - 128;
        float s = 0.f;
        #pragma unroll
        for (int j = 0; j < 64; j++) s += wq[i * 64 + j] * watt[64 + j];
        uv[128 + i] = s;
    }
}

__global__ void prep_wv(const float* __restrict__ wself_a, float* __restrict__ uv)
{
    int k = threadIdx.x;   // 256
    const float* v = uv + 128;
    float s = 0.f;
    #pragma unroll 8
    for (int j = 0; j < 128; j++) s += wself_a[k * 128 + j] * v[j];
    uv[256 + k] = s;
}

// ---------------- CSR build ----------------
__global__ void zero_int(int* __restrict__ p, int n)
{
    int i = blockIdx.x * blockDim.x + threadIdx.x;
    if (i < n) p[i] = 0;
}

// histogram over 4 relations (blockIdx.y selects)
__global__ void hist4(const int* __restrict__ r0, const int* __restrict__ r1,
                      const int* __restrict__ r2, const int* __restrict__ r3,
                      int* __restrict__ degbase)
{
    const int* row = (blockIdx.y == 0) ? r0 : (blockIdx.y == 1) ? r1
                   : (blockIdx.y == 2) ? r2 : r3;
    int* deg = degbase + blockIdx.y * NROW;
    int i = blockIdx.x * blockDim.x + threadIdx.x;
    if (i < EDG) atomicAdd(&deg[row[i]], 1);
}

// exclusive scan per relation: one block per relation (grid = 4 blocks)
__global__ void __launch_bounds__(1024) exscan4(const int* __restrict__ degbase,
                                                int* __restrict__ basebase,
                                                int* __restrict__ curbase)
{
    const int* deg = degbase + blockIdx.x * NROW;
    int* base = basebase + blockIdx.x * (NROW + 1);
    int* cur  = curbase  + blockIdx.x * NROW;

    __shared__ int wsum[32];
    __shared__ int carry;
    int tid = threadIdx.x, lane = tid & 31, wid = tid >> 5;
    if (tid == 0) carry = 0;
    __syncthreads();

    for (int start = 0; start < NROW; start += 1024) {
        int i = start + tid;
        int v = (i < NROW) ? deg[i] : 0;
        int x = v;
        #pragma unroll
        for (int off = 1; off < 32; off <<= 1) {
            int t = __shfl_up_sync(0xffffffffu, x, off);
            if (lane >= off) x += t;
        }
        if (lane == 31) wsum[wid] = x;
        __syncthreads();
        if (wid == 0) {
            int s = wsum[lane];
            #pragma unroll
            for (int off = 1; off < 32; off <<= 1) {
                int t = __shfl_up_sync(0xffffffffu, s, off);
                if (lane >= off) s += t;
            }
            wsum[lane] = s;
        }
        __syncthreads();
        int incl = x + (wid ? wsum[wid - 1] : 0) + carry;
        if (i < NROW) { base[i] = incl - v; cur[i] = incl - v; }
        __syncthreads();
        if (tid == 0) carry += wsum[31];
        __syncthreads();
    }
    if (threadIdx.x == 0) base[NROW] = carry;
}

// scatter edges into packed (col,val) per relation
__global__ void scatter4(const int* __restrict__ r0, const int* __restrict__ c0, const float* __restrict__ v0,
                         const int* __restrict__ r1, const int* __restrict__ c1, const float* __restrict__ v1,
                         const int* __restrict__ r2, const int* __restrict__ c2, const float* __restrict__ v2,
                         const int* __restrict__ r3, const int* __restrict__ c3, const float* __restrict__ v3,
                         int* __restrict__ curbase, int2* __restrict__ epackbase)
{
    const int* row; const int* col; const float* val;
    switch (blockIdx.y) {
        case 0: row = r0; col = c0; val = v0; break;
        case 1: row = r1; col = c1; val = v1; break;
        case 2: row = r2; col = c2; val = v2; break;
        default: row = r3; col = c3; val = v3; break;
    }
    int* cur = curbase + blockIdx.y * NROW;
    int2* ep = epackbase + (size_t)blockIdx.y * EDG;
    int i = blockIdx.x * blockDim.x + threadIdx.x;
    if (i >= EDG) return;
    int r = row[i];
    int pos = atomicAdd(&cur[r], 1);
    ep[pos] = make_int2(col[i], __float_as_int(val[i]));
}

// gather SpMM: warp per dst row, 4 relations via blockIdx.y
__global__ void __launch_bounds__(256) gather4(
    const int2* __restrict__ epackbase, const int* __restrict__ basebase,
    const float* __restrict__ f0, const float* __restrict__ f1,
    const float* __restrict__ f2, const float* __restrict__ f3,
    float* __restrict__ o0, float* __restrict__ o1,
    float* __restrict__ o2, float* __restrict__ o3)
{
    const float* ft; float* out;
    switch (blockIdx.y) {
        case 0: ft = f0; out = o0; break;
        case 1: ft = f1; out = o1; break;
        case 2: ft = f2; out = o2; break;
        default: ft = f3; out = o3; break;
    }
    const int2* ep = epackbase + (size_t)blockIdx.y * EDG;
    const int* base = basebase + blockIdx.y * (NROW + 1);

    int warp = (blockIdx.x * blockDim.x + threadIdx.x) >> 5;
    int lane = threadIdx.x & 31;
    if (warp >= NROW) return;
    int s = base[warp], e = base[warp + 1];

    float4 acc = make_float4(0.f, 0.f, 0.f, 0.f);
    int j = s;
    for (; j + 1 < e; j += 2) {
        int2 p0 = ep[j];
        int2 p1 = ep[j + 1];
        float va = __int_as_float(p0.y);
        float vb = __int_as_float(p1.y);
        float4 fa = ((const float4*)(ft + (size_t)p0.x * 128))[lane];
        float4 fb = ((const float4*)(ft + (size_t)p1.x * 128))[lane];
        acc.x += va * fa.x + vb * fb.x;
        acc.y += va * fa.y + vb * fb.y;
        acc.z += va * fa.z + vb * fb.z;
        acc.w += va * fa.w + vb * fb.w;
    }
    if (j < e) {
        int2 p = ep[j];
        float v = __int_as_float(p.y);
        float4 f = ((const float4*)(ft + (size_t)p.x * 128))[lane];
        acc.x += v * f.x; acc.y += v * f.y; acc.z += v * f.z; acc.w += v * f.w;
    }
    ((float4*)(out + (size_t)warp * 128))[lane] = acc;
}

// ---------------- fused attention: elu + softmax(2) + weighted agg --------
__global__ void __launch_bounds__(256) attn_fuse(
    const float* __restrict__ nbb, const float* __restrict__ nbc,
    const float* __restrict__ xa, const float* __restrict__ uv,
    float* __restrict__ agg, int N)
{
    int warp = (blockIdx.x * blockDim.x + threadIdx.x) >> 5;
    int lane = threadIdx.x & 31;
    if (warp >= N) return;

    float4 b  = ((const float4*)(nbb + (size_t)warp * 128))[lane];
    float4 c  = ((const float4*)(nbc + (size_t)warp * 128))[lane];
    float4 u4 = ((const float4*)uv)[lane];
    float4 x0 = ((const float4*)(xa + (size_t)warp * 256))[lane];
    float4 x1 = ((const float4*)(xa + (size_t)warp * 256))[lane + 32];
    float4 w0 = ((const float4*)(uv + 256))[lane];
    float4 w1 = ((const float4*)(uv + 256))[lane + 32];

    float db = b.x * u4.x + b.y * u4.y + b.z * u4.z + b.w * u4.w;
    float dc = c.x * u4.x + c.y * u4.y + c.z * u4.z + c.w * u4.w;
    float ds = x0.x * w0.x + x0.y * w0.y + x0.z * w0.z + x0.w * w0.w
             + x1.x * w1.x + x1.y * w1.y + x1.z * w1.z + x1.w * w1.w;

    #pragma unroll
    for (int o = 16; o; o >>= 1) {
        db += __shfl_xor_sync(0xffffffffu, db, o);
        dc += __shfl_xor_sync(0xffffffffu, dc, o);
        ds += __shfl_xor_sync(0xffffffffu, ds, o);
    }

    float eb = db + ds;
    float ec = dc + ds;
    eb = (eb > 0.f) ? eb : expm1f(eb);    // elu, alpha=1
    ec = (ec > 0.f) ? ec : expm1f(ec);
    float m  = fmaxf(eb, ec);
    float wb = expf(eb - m);
    float wc = expf(ec - m);
    float ab = wb / (wb + wc);
    float ac = 1.f - ab;

    float4 o4;
    o4.x = ab * b.x + ac * c.x;
    o4.y = ab * b.y + ac * c.y;
    o4.z = ab * b.z + ac * c.z;
    o4.w = ab * b.w + ac * c.w;
    ((float4*)(agg + (size_t)warp * 128))[lane] = o4;
}

// ---------------- launcher ----------------
extern "C" void kernel_launch(void* const* d_in, const int* in_sizes, int n_in,
                              void* d_out, int out_size)
{
    const float* x_a       = (const float*)d_in[0];
    const float* x_b       = (const float*)d_in[1];
    const float* x_c       = (const float*)d_in[2];
    const int*   row_ab    = (const int*)d_in[3];
    const int*   col_ab    = (const int*)d_in[4];
    const float* val_ab    = (const float*)d_in[5];
    const int*   row_ac    = (const int*)d_in[6];
    const int*   col_ac    = (const int*)d_in[7];
    const float* val_ac    = (const float*)d_in[8];
    const int*   row_ba    = (const int*)d_in[9];
    const int*   col_ba    = (const int*)d_in[10];
    const float* val_ba    = (const float*)d_in[11];
    const int*   row_ca    = (const int*)d_in[12];
    const int*   col_ca    = (const int*)d_in[13];
    const float* val_ca    = (const float*)d_in[14];
    const float* w_self_a  = (const float*)d_in[15];
    const float* w_self_b  = (const float*)d_in[16];
    const float* w_self_c  = (const float*)d_in[17];
    const float* W_ab      = (const float*)d_in[18];
    const float* W_ac      = (const float*)d_in[19];
    const float* W_ba      = (const float*)d_in[20];
    const float* W_ca      = (const float*)d_in[21];
    const float* bias_a    = (const float*)d_in[22];
    const float* bias_b    = (const float*)d_in[23];
    const float* bias_c    = (const float*)d_in[24];
    const float* w_cat_a   = (const float*)d_in[25];
    const float* w_cat_b   = (const float*)d_in[26];
    const float* w_cat_c   = (const float*)d_in[27];
    const float* w_query_a = (const float*)d_in[28];
    const float* w_keys_a  = (const float*)d_in[29];
    const float* w_att_a   = (const float*)d_in[30];

    float* scratch = nullptr;
    cudaGetSymbolAddress((void**)&scratch, g_scratch);

    float* nbb   = scratch + 0ull * SZ;
    float* nbc   = scratch + 1ull * SZ;
    float* aggb  = scratch + 2ull * SZ;
    float* aggc  = scratch + 3ull * SZ;
    float* xbWab = scratch + 4ull * SZ;
    float* xcWac = scratch + 5ull * SZ;
    float* xaWba = scratch + 6ull * SZ;
    float* xaWca = scratch + 7ull * SZ;
    float* agga  = scratch + 8ull * SZ;

    unsigned* WT    = (unsigned*)(scratch + OFF_WabT);   // 4 x [128][256]
    unsigned* Wc1T  = (unsigned*)(scratch + OFF_WC1A);   // 3 x [128][128]
    unsigned* WfT   = (unsigned*)(scratch + OFF_WFA);    // 3 x [128][256]
    float*    uv    = scratch + OFF_UV;
    int*      deg   = (int*)(scratch + OFF_DEG);
    int*      base  = (int*)(scratch + OFF_BASE);
    int*      cur   = (int*)(scratch + OFF_CUR);
    int2*     epack = (int2*)(scratch + OFF_EPACK);

    unsigned* WabT = WT + 0 * 256 * 128;
    unsigned* WacT = WT + 1 * 256 * 128;
    unsigned* WbaT = WT + 2 * 256 * 128;
    unsigned* WcaT = WT + 3 * 256 * 128;
    unsigned* Wc1aT = Wc1T + 0 * 128 * 128;
    unsigned* Wc1bT = Wc1T + 1 * 128 * 128;
    unsigned* Wc1cT = Wc1T + 2 * 128 * 128;
    unsigned* WfaT = WfT + 0 * 256 * 128;
    unsigned* WfbT = WfT + 1 * 256 * 128;
    unsigned* WfcT = WfT + 2 * 256 * 128;

    float* out   = (float*)d_out;
    float* out_a = out;
    float* out_b = out + (size_t)NA * DOUT;
    float* out_c = out + (size_t)(NA + NB) * DOUT;

    const int GB  = (NA + 127) / 128;                 // 391
    const int EB  = (EDG + 255) / 256;                // 3125
    const int ATB = (NA * 32 + 255) / 256;            // 6250
    const int GWB = (NROW * 32 + 255) / 256;          // 6250

    // ---- weight prep (3 launches) + uv ----
    prep_uv<<<1, 256>>>(w_query_a, w_keys_a, w_att_a, uv);
    prep_wv<<<1, 256>>>(w_self_a, uv);
    transpose256_4<<<dim3(128, 4), 256>>>(W_ab, W_ac, W_ba, W_ca, WT);
    transpose128_3<<<dim3(64, 3), 256>>>(w_cat_a, w_cat_b, w_cat_c, Wc1T);
    fold3<<<dim3(128, 3), 256>>>(w_self_a, w_self_b, w_self_c,
                                 w_cat_a, w_cat_b, w_cat_c, WfT);

    // ---- CSR build for all 4 relations ----
    zero_int<<<(4 * NROW + 255) / 256, 256>>>(deg, 4 * NROW);
    hist4<<<dim3(EB, 4), 256>>>(row_ab, row_ac, row_ba, row_ca, deg);
    exscan4<<<4, 1024>>>(deg, base, cur);
    scatter4<<<dim3(EB, 4), 256>>>(row_ab, col_ab, val_ab,
                                   row_ac, col_ac, val_ac,
                                   row_ba, col_ba, val_ba,
                                   row_ca, col_ca, val_ca,
                                   cur, epack);

    // ---- projection GEMMs ----
    gemm_tf32<<<GB, 256>>>(x_b, 256, nullptr, 0, WabT, 256, nullptr, 0, nullptr, xbWab, NB, 256);
    gemm_tf32<<<GB, 256>>>(x_c, 256, nullptr, 0, WacT, 256, nullptr, 0, nullptr, xcWac, NC, 256);
    gemm_tf32<<<GB, 256>>>(x_a, 256, nullptr, 0, WbaT, 256, nullptr, 0, nullptr, xaWba, NA, 256);
    gemm_tf32<<<GB, 256>>>(x_a, 256, nullptr, 0, WcaT, 256, nullptr, 0, nullptr, xaWca, NA, 256);

    // ---- gather SpMM (all 4 relations, no atomics) ----
    gather4<<<dim3(GWB, 4), 256>>>(epack, base,
                                   xbWab, xcWac, xaWba, xaWca,
                                   nbb, nbc, aggb, aggc);

    // ---- attention fusion for type 'a' ----
    attn_fuse<<<ATB, 256>>>(nbb, nbc, x_a, uv, agga, NA);

    // ---- output GEMMs: [agg | x] @ [wcat1 ; Wfold] + bias, K=384 ----
    gemm_tf32<<<GB, 256>>>(agga, 128, x_a, 256, Wc1aT, 128, WfaT, 256, bias_a, out_a, NA, 384);
    gemm_tf32<<<GB, 256>>>(aggb, 128, x_b, 256, Wc1bT, 128, WfbT, 256, bias_b, out_b, NB, 384);
    gemm_tf32<<<GB, 256>>>(aggc, 128, x_c, 256, Wc1cT, 128, WfcT, 256, bias_c, out_c, NC, 384);
}

// round 6
// speedup vs baseline: 3.9781x; 1.2715x over previous
#include <cuda_runtime.h>
#include <cuda_fp16.h>
#include <cstdint>
#include <cstddef>

// ---------------- problem constants ----------------
#define NA 50000
#define NROW 50000
#define EDG 800000
#define DOUT 128
#define SZ (50000 * 128)        // floats per [N,128] fp32 buffer
#define FTSZ (50000 * 128)      // halves per [N,128] fp16 buffer

// scratch layout (floats):
//  slot 0: agga, slot 1: aggb, slot 2: aggc   (fp32)
//  slots 4-5: 4 x fp16 projection outputs (4 * 6.4M halves = 2 float slots)
//  then tf32 weights, uv, CSR arrays
#define W_OFF      (6ull * SZ)
#define OFF_WT     (W_OFF)                       // 4 * 256*128 tf32
#define OFF_WC1    (OFF_WT  + 4*256*128)         // 3 * 128*128
#define OFF_WF     (OFF_WC1 + 3*128*128)         // 3 * 256*128
#define OFF_UV     (OFF_WF  + 3*256*128)         // 512
#define OFF_DEG    (OFF_UV   + 512)              // 4 * 50000 ints
#define OFF_BASE   (OFF_DEG  + 4*50000)          // 4 * 50001 ints
#define OFF_CUR    (OFF_BASE + 4*50004)          // 4 * 50000 ints
#define OFF_EPACK  (((OFF_CUR + 4*50000) + 1) & ~1ull)  // 4 * EDG int2
#define SCRATCH_TOTAL (OFF_EPACK + 4ull*EDG*2)

__device__ float g_scratch[SCRATCH_TOTAL];

// ---------------- helpers ----------------
__device__ __forceinline__ unsigned f2tf(float x) {
    unsigned u; asm("cvt.rna.tf32.f32 %0, %1;" : "=r"(u) : "f"(x)); return u;
}

__device__ __forceinline__ void ldsm4(unsigned &r0, unsigned &r1, unsigned &r2,
                                      unsigned &r3, unsigned addr) {
    asm volatile("ldmatrix.sync.aligned.m8n8.x4.shared.b16 {%0,%1,%2,%3}, [%4];"
                 : "=r"(r0), "=r"(r1), "=r"(r2), "=r"(r3) : "r"(addr));
}

__device__ __forceinline__ void mma_tf32(float c[4], const unsigned a[4],
                                         unsigned b0, unsigned b1) {
    asm volatile(
        "mma.sync.aligned.m16n8k8.row.col.f32.tf32.tf32.f32 "
        "{%0,%1,%2,%3}, {%4,%5,%6,%7}, {%8,%9}, {%0,%1,%2,%3};"
        : "+f"(c[0]), "+f"(c[1]), "+f"(c[2]), "+f"(c[3])
        : "r"(a[0]), "r"(a[1]), "r"(a[2]), "r"(a[3]), "r"(b0), "r"(b1));
}

__device__ __forceinline__ void cpasync16(void* sdst, const void* gsrc, int nbytes) {
    unsigned s = (unsigned)__cvta_generic_to_shared(sdst);
    asm volatile("cp.async.cg.shared.global [%0], [%1], 16, %2;\n"
                 :: "r"(s), "l"(gsrc), "r"(nbytes));
}

// ---------------- tf32 tensor-core GEMM body, cp.async 2-stage -------------
// A fed to mma as raw fp32 bits (HW truncates to tf32). B pre-converted tf32.
template<int K, bool SPLIT, bool HOUT>
__device__ __forceinline__ void gemm_body(
    const float* __restrict__ A0, int lda0,
    const float* __restrict__ A1, int lda1,
    const unsigned* __restrict__ B0T, int ldb0,
    const unsigned* __restrict__ B1T, int ldb1,
    const float* __restrict__ bias,
    float* __restrict__ Yf, __half* __restrict__ Yh, int N)
{
    __shared__ float    As[2][128][20];   // 16 k + 4 pad
    __shared__ unsigned Bs[2][128][20];

    const int tid  = threadIdx.x;
    const int lane = tid & 31;
    const int w    = tid >> 5;
    const int bm   = blockIdx.x * 128;

    const int wm = (w >> 2) * 64;
    const int wn = (w & 3) * 32;

    const int a_mo = ((lane >> 3) & 1) * 8 + (lane & 7);
    const int a_ko = (lane >> 4) * 4;
    const int b_no = (lane >> 4) * 8 + (lane & 7);
    const int b_ko = ((lane >> 3) & 1) * 4;

    float acc[4][4][4];
    #pragma unroll
    for (int i = 0; i < 4; i++)
        #pragma unroll
        for (int j = 0; j < 4; j++)
            #pragma unroll
            for (int c = 0; c < 4; c++) acc[i][j][c] = 0.f;

    constexpr int NK = K >> 4;

    auto stage = [&](int buf, int k0) {
        const float* asrc; int ld, colb;
        if (SPLIT && k0 >= 128) { asrc = A1; ld = lda1; colb = k0 - 128; }
        else                    { asrc = A0; ld = lda0; colb = k0; }
        #pragma unroll
        for (int i = 0; i < 2; i++) {
            int slot = tid + i * 256;
            int r = slot >> 2, c = (slot & 3) * 4;
            int grow = bm + r;
            const float* src = asrc + (size_t)(grow < N ? grow : 0) * ld + colb + c;
            cpasync16(&As[buf][r][c], src, grow < N ? 16 : 0);
        }
        const unsigned* bsrc; int ldb;
        if (SPLIT && k0 >= 128) { bsrc = B1T + (k0 - 128); ldb = ldb1; }
        else                    { bsrc = B0T + k0;         ldb = ldb0; }
        #pragma unroll
        for (int i = 0; i < 2; i++) {
            int slot = tid + i * 256;
            int n = slot >> 2, c = (slot & 3) * 4;
            cpasync16(&Bs[buf][n][c], bsrc + (size_t)n * ldb + c, 16);
        }
        asm volatile("cp.async.commit_group;\n" ::);
    };

    stage(0, 0);

    for (int kt = 0; kt < NK; kt++) {
        if (kt + 1 < NK) {
            stage((kt + 1) & 1, (kt + 1) * 16);
            asm volatile("cp.async.wait_group 1;\n" ::);
        } else {
            asm volatile("cp.async.wait_group 0;\n" ::);
        }
        __syncthreads();

        const int buf = kt & 1;
        #pragma unroll
        for (int ks = 0; ks < 2; ks++) {
            const int k8 = ks * 8;
            unsigned a[4][4], b0[4], b1[4];
            #pragma unroll
            for (int mt = 0; mt < 4; mt++) {
                unsigned addr = (unsigned)__cvta_generic_to_shared(
                    &As[buf][wm + mt * 16 + a_mo][k8 + a_ko]);
                ldsm4(a[mt][0], a[mt][1], a[mt][2], a[mt][3], addr);
            }
            #pragma unroll
            for (int np = 0; np < 2; np++) {
                unsigned addr = (unsigned)__cvta_generic_to_shared(
                    &Bs[buf][wn + np * 16 + b_no][k8 + b_ko]);
                ldsm4(b0[np * 2], b1[np * 2], b0[np * 2 + 1], b1[np * 2 + 1], addr);
            }
            #pragma unroll
            for (int mt = 0; mt < 4; mt++)
                #pragma unroll
                for (int nt = 0; nt < 4; nt++)
                    mma_tf32(acc[mt][nt], a[mt], b0[nt], b1[nt]);
        }
        __syncthreads();
    }

    // ---- epilogue ----
    const int g = lane >> 2, tg = lane & 3;
    #pragma unroll
    for (int nt = 0; nt < 4; nt++) {
        int cc = wn + nt * 8 + tg * 2;
        float bx = bias ? bias[cc]     : 0.f;
        float by = bias ? bias[cc + 1] : 0.f;
        #pragma unroll
        for (int mt = 0; mt < 4; mt++) {
            int r = bm + wm + mt * 16 + g;
            if (r < N) {
                if (HOUT) {
                    *(__half2*)(Yh + (size_t)r * 128 + cc) =
                        __floats2half2_rn(acc[mt][nt][0], acc[mt][nt][1]);
                } else {
                    *(float2*)(Yf + (size_t)r * 128 + cc) =
                        make_float2(acc[mt][nt][0] + bx, acc[mt][nt][1] + by);
                }
            }
            if (r + 8 < N) {
                if (HOUT) {
                    *(__half2*)(Yh + (size_t)(r + 8) * 128 + cc) =
                        __floats2half2_rn(acc[mt][nt][2], acc[mt][nt][3]);
                } else {
                    *(float2*)(Yf + (size_t)(r + 8) * 128 + cc) =
                        make_float2(acc[mt][nt][2] + bx, acc[mt][nt][3] + by);
                }
            }
        }
    }
}

// 4 projection GEMMs in one launch: y=0:x_b@Wab, 1:x_c@Wac, 2:x_a@Wba, 3:x_a@Wca
__global__ void __launch_bounds__(256, 2) gemm_proj(
    const float* __restrict__ xa, const float* __restrict__ xb,
    const float* __restrict__ xc, const unsigned* __restrict__ WT,
    __half* __restrict__ yh)
{
    int y = blockIdx.y;
    const float* A0 = (y == 0) ? xb : (y == 1) ? xc : xa;
    gemm_body<256, false, true>(A0, 256, nullptr, 0,
                                WT + (size_t)y * 256 * 128, 256, nullptr, 0,
                                nullptr, nullptr, yh + (size_t)y * FTSZ, NA);
}

// 3 output GEMMs in one launch: [agg | x] @ [wcat1 ; Wfold] + bias
__global__ void __launch_bounds__(256, 2) gemm_out(
    const float* __restrict__ aggbase,
    const float* __restrict__ xa, const float* __restrict__ xb,
    const float* __restrict__ xc,
    const unsigned* __restrict__ Wc1T, const unsigned* __restrict__ WfT,
    const float* __restrict__ ba, const float* __restrict__ bb,
    const float* __restrict__ bc, float* __restrict__ out)
{
    int y = blockIdx.y;
    const float* A1 = (y == 0) ? xa : (y == 1) ? xb : xc;
    const float* bias = (y == 0) ? ba : (y == 1) ? bb : bc;
    gemm_body<384, true, false>(aggbase + (size_t)y * SZ, 128, A1, 256,
                                Wc1T + (size_t)y * 128 * 128, 128,
                                WfT + (size_t)y * 256 * 128, 256,
                                bias, out + (size_t)y * NA * 128, nullptr, NA);
}

// ---------------- weight prep ----------------
__global__ void transpose256_4(const float* __restrict__ w0, const float* __restrict__ w1,
                               const float* __restrict__ w2, const float* __restrict__ w3,
                               unsigned* __restrict__ outbase)
{
    const float* in = (blockIdx.y == 0) ? w0 : (blockIdx.y == 1) ? w1
                    : (blockIdx.y == 2) ? w2 : w3;
    unsigned* out = outbase + (size_t)blockIdx.y * 256 * 128;
    int idx = blockIdx.x * blockDim.x + threadIdx.x;
    if (idx >= 256 * 128) return;
    int k = idx >> 7, n = idx & 127;
    out[(size_t)n * 256 + k] = f2tf(in[(size_t)k * 128 + n]);
}

__global__ void transpose128_3(const float* __restrict__ w0, const float* __restrict__ w1,
                               const float* __restrict__ w2, unsigned* __restrict__ outbase)
{
    const float* in = (blockIdx.y == 0) ? w0 : (blockIdx.y == 1) ? w1 : w2;
    unsigned* out = outbase + (size_t)blockIdx.y * 128 * 128;
    int idx = blockIdx.x * blockDim.x + threadIdx.x;
    if (idx >= 128 * 128) return;
    int k = idx >> 7, n = idx & 127;
    out[(size_t)n * 128 + k] = f2tf(in[(size_t)k * 128 + n]);
}

__global__ void fold3(const float* __restrict__ ws0, const float* __restrict__ ws1,
                      const float* __restrict__ ws2,
                      const float* __restrict__ wc0, const float* __restrict__ wc1,
                      const float* __restrict__ wc2, unsigned* __restrict__ outbase)
{
    const float* wself = (blockIdx.y == 0) ? ws0 : (blockIdx.y == 1) ? ws1 : ws2;
    const float* wcat  = (blockIdx.y == 0) ? wc0 : (blockIdx.y == 1) ? wc1 : wc2;
    unsigned* outT = outbase + (size_t)blockIdx.y * 256 * 128;
    int idx = blockIdx.x * blockDim.x + threadIdx.x;
    if (idx >= 256 * 128) return;
    int k = idx >> 7, n = idx & 127;
    const float* w2 = wcat + 128 * 128;
    float s = 0.f;
    #pragma unroll 8
    for (int j = 0; j < 128; j++) s += wself[k * 128 + j] * w2[j * 128 + n];
    outT[(size_t)n * 256 + k] = f2tf(s);
}

__global__ void prep_uv(const float* __restrict__ wq, const float* __restrict__ wk,
                        const float* __restrict__ watt, float* __restrict__ uv)
{
    int t = threadIdx.x;
    if (t < 128) {
        float s = 0.f;
        #pragma unroll
        for (int j = 0; j < 64; j++) s += wk[t * 64 + j] * watt[j];
        uv[t] = s;
    } else {
        int i = t - 128;
        float s = 0.f;
        #pragma unroll
        for (int j = 0; j < 64; j++) s += wq[i * 64 + j] * watt[64 + j];
        uv[128 + i] = s;
    }
}

__global__ void prep_wv(const float* __restrict__ wself_a, float* __restrict__ uv)
{
    int k = threadIdx.x;
    const float* v = uv + 128;
    float s = 0.f;
    #pragma unroll 8
    for (int j = 0; j < 128; j++) s += wself_a[k * 128 + j] * v[j];
    uv[256 + k] = s;
}

// ---------------- CSR build ----------------
__global__ void zero_int(int* __restrict__ p, int n)
{
    int i = blockIdx.x * blockDim.x + threadIdx.x;
    if (i < n) p[i] = 0;
}

__global__ void hist4(const int* __restrict__ r0, const int* __restrict__ r1,
                      const int* __restrict__ r2, const int* __restrict__ r3,
                      int* __restrict__ degbase)
{
    const int* row = (blockIdx.y == 0) ? r0 : (blockIdx.y == 1) ? r1
                   : (blockIdx.y == 2) ? r2 : r3;
    int* deg = degbase + blockIdx.y * NROW;
    int i = blockIdx.x * blockDim.x + threadIdx.x;
    if (i < EDG) atomicAdd(&deg[row[i]], 1);
}

__global__ void __launch_bounds__(1024) exscan4(const int* __restrict__ degbase,
                                                int* __restrict__ basebase,
                                                int* __restrict__ curbase)
{
    const int* deg = degbase + blockIdx.x * NROW;
    int* base = basebase + blockIdx.x * (NROW + 1);
    int* cur  = curbase  + blockIdx.x * NROW;

    __shared__ int wsum[32];
    __shared__ int carry;
    int tid = threadIdx.x, lane = tid & 31, wid = tid >> 5;
    if (tid == 0) carry = 0;
    __syncthreads();

    for (int start = 0; start < NROW; start += 1024) {
        int i = start + tid;
        int v = (i < NROW) ? deg[i] : 0;
        int x = v;
        #pragma unroll
        for (int off = 1; off < 32; off <<= 1) {
            int t = __shfl_up_sync(0xffffffffu, x, off);
            if (lane >= off) x += t;
        }
        if (lane == 31) wsum[wid] = x;
        __syncthreads();
        if (wid == 0) {
            int s = wsum[lane];
            #pragma unroll
            for (int off = 1; off < 32; off <<= 1) {
                int t = __shfl_up_sync(0xffffffffu, s, off);
                if (lane >= off) s += t;
            }
            wsum[lane] = s;
        }
        __syncthreads();
        int incl = x + (wid ? wsum[wid - 1] : 0) + carry;
        if (i < NROW) { base[i] = incl - v; cur[i] = incl - v; }
        __syncthreads();
        if (tid == 0) carry += wsum[31];
        __syncthreads();
    }
    if (threadIdx.x == 0) base[NROW] = carry;
}

__global__ void scatter4(const int* __restrict__ r0, const int* __restrict__ c0, const float* __restrict__ v0,
                         const int* __restrict__ r1, const int* __restrict__ c1, const float* __restrict__ v1,
                         const int* __restrict__ r2, const int* __restrict__ c2, const float* __restrict__ v2,
                         const int* __restrict__ r3, const int* __restrict__ c3, const float* __restrict__ v3,
                         int* __restrict__ curbase, int2* __restrict__ epackbase)
{
    const int* row; const int* col; const float* val;
    switch (blockIdx.y) {
        case 0: row = r0; col = c0; val = v0; break;
        case 1: row = r1; col = c1; val = v1; break;
        case 2: row = r2; col = c2; val = v2; break;
        default: row = r3; col = c3; val = v3; break;
    }
    int* cur = curbase + blockIdx.y * NROW;
    int2* ep = epackbase + (size_t)blockIdx.y * EDG;
    int i = blockIdx.x * blockDim.x + threadIdx.x;
    if (i >= EDG) return;
    int r = row[i];
    int pos = atomicAdd(&cur[r], 1);
    ep[pos] = make_int2(col[i], __float_as_int(val[i]));
}

// ---------------- gather (fp16 features) ----------------
__device__ __forceinline__ float4 gather_row(
    const int2* __restrict__ ep, const int* __restrict__ base,
    int r, const __half* __restrict__ ft, int lane)
{
    int s = base[r], e = base[r + 1];
    float4 acc = make_float4(0.f, 0.f, 0.f, 0.f);
    int j = s;
    for (; j + 1 < e; j += 2) {
        int2 p0 = ep[j];
        int2 p1 = ep[j + 1];
        float va = __int_as_float(p0.y);
        float vb = __int_as_float(p1.y);
        const __half2* ra = (const __half2*)(ft + (size_t)p0.x * 128);
        const __half2* rb = (const __half2*)(ft + (size_t)p1.x * 128);
        float2 a0 = __half22float2(ra[lane * 2]);
        float2 a1 = __half22float2(ra[lane * 2 + 1]);
        float2 b0 = __half22float2(rb[lane * 2]);
        float2 b1 = __half22float2(rb[lane * 2 + 1]);
        acc.x += va * a0.x + vb * b0.x;
        acc.y += va * a0.y + vb * b0.y;
        acc.z += va * a1.x + vb * b1.x;
        acc.w += va * a1.y + vb * b1.y;
    }
    if (j < e) {
        int2 p = ep[j];
        float v = __int_as_float(p.y);
        const __half2* rp = (const __half2*)(ft + (size_t)p.x * 128);
        float2 l0 = __half22float2(rp[lane * 2]);
        float2 l1 = __half22float2(rp[lane * 2 + 1]);
        acc.x += v * l0.x; acc.y += v * l0.y;
        acc.z += v * l1.x; acc.w += v * l1.y;
    }
    return acc;
}

// fused: gather rel0 (nb_b) + rel1 (nb_c) + attention -> agga
__global__ void __launch_bounds__(256) gather_attn(
    const int2* __restrict__ epack, const int* __restrict__ basebase,
    const __half* __restrict__ ftbase, const float* __restrict__ xa,
    const float* __restrict__ uv, float* __restrict__ agga)
{
    int warp = (blockIdx.x * blockDim.x + threadIdx.x) >> 5;
    int lane = threadIdx.x & 31;
    if (warp >= NROW) return;

    float4 b = gather_row(epack,       basebase,             warp, ftbase,        lane);
    float4 c = gather_row(epack + EDG, basebase + (NROW + 1), warp, ftbase + FTSZ, lane);

    float4 u4 = ((const float4*)uv)[lane];
    float4 x0 = ((const float4*)(xa + (size_t)warp * 256))[lane];
    float4 x1 = ((const float4*)(xa + (size_t)warp * 256))[lane + 32];
    float4 w0 = ((const float4*)(uv + 256))[lane];
    float4 w1 = ((const float4*)(uv + 256))[lane + 32];

    float db = b.x * u4.x + b.y * u4.y + b.z * u4.z + b.w * u4.w;
    float dc = c.x * u4.x + c.y * u4.y + c.z * u4.z + c.w * u4.w;
    float ds = x0.x * w0.x + x0.y * w0.y + x0.z * w0.z + x0.w * w0.w
             + x1.x * w1.x + x1.y * w1.y + x1.z * w1.z + x1.w * w1.w;

    #pragma unroll
    for (int o = 16; o; o >>= 1) {
        db += __shfl_xor_sync(0xffffffffu, db, o);
        dc += __shfl_xor_sync(0xffffffffu, dc, o);
        ds += __shfl_xor_sync(0xffffffffu, ds, o);
    }

    float eb = db + ds;
    float ec = dc + ds;
    eb = (eb > 0.f) ? eb : expm1f(eb);
    ec = (ec > 0.f) ? ec : expm1f(ec);
    float m  = fmaxf(eb, ec);
    float wb = expf(eb - m);
    float wc = expf(ec - m);
    float ab = wb / (wb + wc);
    float ac = 1.f - ab;

    float4 o4;
    o4.x = ab * b.x + ac * c.x;
    o4.y = ab * b.y + ac * c.y;
    o4.z = ab * b.z + ac * c.z;
    o4.w = ab * b.w + ac * c.w;
    ((float4*)(agga + (size_t)warp * 128))[lane] = o4;
}

// rel2 -> aggb, rel3 -> aggc (blockIdx.y)
__global__ void __launch_bounds__(256) gather2(
    const int2* __restrict__ epack, const int* __restrict__ basebase,
    const __half* __restrict__ ftbase, float* __restrict__ aggbase)
{
    int rel = 2 + blockIdx.y;
    const int2* ep = epack + (size_t)rel * EDG;
    const int* base = basebase + rel * (NROW + 1);
    const __half* ft = ftbase + (size_t)rel * FTSZ;
    float* out = aggbase + (size_t)(1 + blockIdx.y) * SZ;

    int warp = (blockIdx.x * blockDim.x + threadIdx.x) >> 5;
    int lane = threadIdx.x & 31;
    if (warp >= NROW) return;
    float4 acc = gather_row(ep, base, warp, ft, lane);
    ((float4*)(out + (size_t)warp * 128))[lane] = acc;
}

// ---------------- launcher ----------------
extern "C" void kernel_launch(void* const* d_in, const int* in_sizes, int n_in,
                              void* d_out, int out_size)
{
    const float* x_a       = (const float*)d_in[0];
    const float* x_b       = (const float*)d_in[1];
    const float* x_c       = (const float*)d_in[2];
    const int*   row_ab    = (const int*)d_in[3];
    const int*   col_ab    = (const int*)d_in[4];
    const float* val_ab    = (const float*)d_in[5];
    const int*   row_ac    = (const int*)d_in[6];
    const int*   col_ac    = (const int*)d_in[7];
    const float* val_ac    = (const float*)d_in[8];
    const int*   row_ba    = (const int*)d_in[9];
    const int*   col_ba    = (const int*)d_in[10];
    const float* val_ba    = (const float*)d_in[11];
    const int*   row_ca    = (const int*)d_in[12];
    const int*   col_ca    = (const int*)d_in[13];
    const float* val_ca    = (const float*)d_in[14];
    const float* w_self_a  = (const float*)d_in[15];
    const float* w_self_b  = (const float*)d_in[16];
    const float* w_self_c  = (const float*)d_in[17];
    const float* W_ab      = (const float*)d_in[18];
    const float* W_ac      = (const float*)d_in[19];
    const float* W_ba      = (const float*)d_in[20];
    const float* W_ca      = (const float*)d_in[21];
    const float* bias_a    = (const float*)d_in[22];
    const float* bias_b    = (const float*)d_in[23];
    const float* bias_c    = (const float*)d_in[24];
    const float* w_cat_a   = (const float*)d_in[25];
    const float* w_cat_b   = (const float*)d_in[26];
    const float* w_cat_c   = (const float*)d_in[27];
    const float* w_query_a = (const float*)d_in[28];
    const float* w_keys_a  = (const float*)d_in[29];
    const float* w_att_a   = (const float*)d_in[30];

    float* scratch = nullptr;
    cudaGetSymbolAddress((void**)&scratch, g_scratch);

    float*    aggbase = scratch;                          // agga, aggb, aggc
    __half*   fth     = (__half*)(scratch + 4ull * SZ);   // 4 fp16 feature bufs
    unsigned* WT      = (unsigned*)(scratch + OFF_WT);
    unsigned* Wc1T    = (unsigned*)(scratch + OFF_WC1);
    unsigned* WfT     = (unsigned*)(scratch + OFF_WF);
    float*    uv      = scratch + OFF_UV;
    int*      deg     = (int*)(scratch + OFF_DEG);
    int*      base    = (int*)(scratch + OFF_BASE);
    int*      cur     = (int*)(scratch + OFF_CUR);
    int2*     epack   = (int2*)(scratch + OFF_EPACK);

    float* out = (float*)d_out;

    const int GB  = (NA + 127) / 128;        // 391
    const int EB  = (EDG + 255) / 256;       // 3125
    const int GWB = (NROW * 32 + 255) / 256; // 6250

    // ---- weight prep ----
    prep_uv<<<1, 256>>>(w_query_a, w_keys_a, w_att_a, uv);
    prep_wv<<<1, 256>>>(w_self_a, uv);
    transpose256_4<<<dim3(128, 4), 256>>>(W_ab, W_ac, W_ba, W_ca, WT);
    transpose128_3<<<dim3(64, 3), 256>>>(w_cat_a, w_cat_b, w_cat_c, Wc1T);
    fold3<<<dim3(128, 3), 256>>>(w_self_a, w_self_b, w_self_c,
                                 w_cat_a, w_cat_b, w_cat_c, WfT);

    // ---- CSR build ----
    zero_int<<<(4 * NROW + 255) / 256, 256>>>(deg, 4 * NROW);
    hist4<<<dim3(EB, 4), 256>>>(row_ab, row_ac, row_ba, row_ca, deg);
    exscan4<<<4, 1024>>>(deg, base, cur);
    scatter4<<<dim3(EB, 4), 256>>>(row_ab, col_ab, val_ab,
                                   row_ac, col_ac, val_ac,
                                   row_ba, col_ba, val_ba,
                                   row_ca, col_ca, val_ca,
                                   cur, epack);

    // ---- 4 projection GEMMs (one launch, fp16 outputs) ----
    gemm_proj<<<dim3(GB, 4), 256>>>(x_a, x_b, x_c, WT, fth);

    // ---- gathers: rel0+rel1 fused with attention -> agga; rel2/3 -> aggb/c ----
    gather_attn<<<GWB, 256>>>(epack, base, fth, x_a, uv, aggbase);
    gather2<<<dim3(GWB, 2), 256>>>(epack, base, fth, aggbase);

    // ---- 3 output GEMMs (one launch) ----
    gemm_out<<<dim3(GB, 3), 256>>>(aggbase, x_a, x_b, x_c, Wc1T, WfT,
                                   bias_a, bias_b, bias_c, out);
}

// round 7
// speedup vs baseline: 4.1794x; 1.0506x over previous
#include <cuda_runtime.h>
#include <cuda_fp16.h>
#include <cstdint>
#include <cstddef>

// ---------------- problem constants ----------------
#define NA 50000
#define NROW 50000
#define EDG 800000
#define SZ (50000 * 128)        // floats per [N,128] fp32 buffer
#define XQ4 3200000             // float4 count per x array (50000*256/4)

// scratch layout (float units):
//  slots 0-2 : agga, aggb, aggc (fp32)
//  slots 3-4 : fth  = 4 x [N,128] fp16 projection outputs
//  slots 5-7 : xh   = 3 x [N,256] fp16 copies of x_a/x_b/x_c
#define OFF_FTH    (3ull * SZ)
#define OFF_XH     (5ull * SZ)
#define W_OFF      (8ull * SZ)
#define OFF_WH     (W_OFF)                        // 4*256*128 halves = 65536 floats
#define OFF_WC1    (OFF_WH  + 65536)              // 3*128*128 tf32
#define OFF_WF     (OFF_WC1 + 3*128*128)          // 3*256*128 tf32
#define OFF_UV     (OFF_WF  + 3*256*128)          // 512
#define OFF_DEG    (OFF_UV   + 512)
#define OFF_BASE   (OFF_DEG  + 4*50000)
#define OFF_CUR    (OFF_BASE + 4*50004)
#define OFF_EPACK  (((OFF_CUR + 4*50000) + 1) & ~1ull)
#define SCRATCH_TOTAL (OFF_EPACK + 4ull*EDG*2)

__device__ float g_scratch[SCRATCH_TOTAL];

// ---------------- helpers ----------------
__device__ __forceinline__ unsigned f2tf(float x) {
    unsigned u; asm("cvt.rna.tf32.f32 %0, %1;" : "=r"(u) : "f"(x)); return u;
}

__device__ __forceinline__ void ldsm4(unsigned &r0, unsigned &r1, unsigned &r2,
                                      unsigned &r3, unsigned addr) {
    asm volatile("ldmatrix.sync.aligned.m8n8.x4.shared.b16 {%0,%1,%2,%3}, [%4];"
                 : "=r"(r0), "=r"(r1), "=r"(r2), "=r"(r3) : "r"(addr));
}

__device__ __forceinline__ void ldsm4t(unsigned &r0, unsigned &r1, unsigned &r2,
                                       unsigned &r3, unsigned addr) {
    asm volatile("ldmatrix.sync.aligned.m8n8.x4.trans.shared.b16 {%0,%1,%2,%3}, [%4];"
                 : "=r"(r0), "=r"(r1), "=r"(r2), "=r"(r3) : "r"(addr));
}

__device__ __forceinline__ void mma_tf32(float c[4], const unsigned a[4],
                                         unsigned b0, unsigned b1) {
    asm volatile(
        "mma.sync.aligned.m16n8k8.row.col.f32.tf32.tf32.f32 "
        "{%0,%1,%2,%3}, {%4,%5,%6,%7}, {%8,%9}, {%0,%1,%2,%3};"
        : "+f"(c[0]), "+f"(c[1]), "+f"(c[2]), "+f"(c[3])
        : "r"(a[0]), "r"(a[1]), "r"(a[2]), "r"(a[3]), "r"(b0), "r"(b1));
}

__device__ __forceinline__ void mma_f16(float c[4], const unsigned a[4],
                                        unsigned b0, unsigned b1) {
    asm volatile(
        "mma.sync.aligned.m16n8k16.row.col.f32.f16.f16.f32 "
        "{%0,%1,%2,%3}, {%4,%5,%6,%7}, {%8,%9}, {%0,%1,%2,%3};"
        : "+f"(c[0]), "+f"(c[1]), "+f"(c[2]), "+f"(c[3])
        : "r"(a[0]), "r"(a[1]), "r"(a[2]), "r"(a[3]), "r"(b0), "r"(b1));
}

__device__ __forceinline__ void cpasync16(void* sdst, const void* gsrc, int nbytes) {
    unsigned s = (unsigned)__cvta_generic_to_shared(sdst);
    asm volatile("cp.async.cg.shared.global [%0], [%1], 16, %2;\n"
                 :: "r"(s), "l"(gsrc), "r"(nbytes));
}

// ================= fp16 projection GEMM body ==============================
// Y[N,128] fp16 = Ah[N,256] fp16 @ Bh[256,128] fp16  (fp32 accum)
__device__ __forceinline__ void gemm_proj_body(
    const __half* __restrict__ Ah, const __half* __restrict__ Bh,
    __half* __restrict__ Yh, int bx)
{
    __shared__ __half As[2][128][40];    // 32 k + 8 pad
    __shared__ __half Bs[2][32][136];    // [k][n], 128 n + 8 pad

    const int tid  = threadIdx.x;
    const int lane = tid & 31;
    const int w    = tid >> 5;
    const int bm   = bx * 128;

    const int wm = (w >> 2) * 64;
    const int wn = (w & 3) * 32;

    float acc[4][4][4];
    #pragma unroll
    for (int i = 0; i < 4; i++)
        #pragma unroll
        for (int j = 0; j < 4; j++)
            #pragma unroll
            for (int c = 0; c < 4; c++) acc[i][j][c] = 0.f;

    auto stage = [&](int buf, int k0) {
        // A: 128 rows x 32 halves = 512 16B chunks, 2/thread
        #pragma unroll
        for (int i = 0; i < 2; i++) {
            int slot = tid + i * 256;
            int r = slot >> 2, c = (slot & 3) * 8;
            int grow = bm + r;
            const __half* src = Ah + (size_t)(grow < NA ? grow : 0) * 256 + k0 + c;
            cpasync16(&As[buf][r][c], src, grow < NA ? 16 : 0);
        }
        // B: 32 k-rows x 128 halves = 512 chunks, 2/thread
        #pragma unroll
        for (int i = 0; i < 2; i++) {
            int slot = tid + i * 256;
            int r = slot >> 4, c = (slot & 15) * 8;
            cpasync16(&Bs[buf][r][c], Bh + (size_t)(k0 + r) * 128 + c, 16);
        }
        asm volatile("cp.async.commit_group;\n" ::);
    };

    stage(0, 0);

    for (int kt = 0; kt < 8; kt++) {        // 8 tiles of k=32
        if (kt + 1 < 8) {
            stage((kt + 1) & 1, (kt + 1) * 32);
            asm volatile("cp.async.wait_group 1;\n" ::);
        } else {
            asm volatile("cp.async.wait_group 0;\n" ::);
        }
        __syncthreads();

        const int buf = kt & 1;
        #pragma unroll
        for (int ks = 0; ks < 2; ks++) {
            const int k16 = ks * 16;
            unsigned a[4][4], b0[4], b1[4];
            #pragma unroll
            for (int mt = 0; mt < 4; mt++) {
                unsigned addr = (unsigned)__cvta_generic_to_shared(
                    &As[buf][wm + mt * 16 + (lane & 15)][k16 + (lane >> 4) * 8]);
                ldsm4(a[mt][0], a[mt][1], a[mt][2], a[mt][3], addr);
            }
            #pragma unroll
            for (int np = 0; np < 2; np++) {
                unsigned addr = (unsigned)__cvta_generic_to_shared(
                    &Bs[buf][k16 + (lane & 15)][wn + np * 16 + (lane >> 4) * 8]);
                // trans: r0=(n sub 2np, k0-7) r1=(n sub 2np, k8-15) r2/r3 = next n sub
                ldsm4t(b0[np * 2], b1[np * 2], b0[np * 2 + 1], b1[np * 2 + 1], addr);
            }
            #pragma unroll
            for (int mt = 0; mt < 4; mt++)
                #pragma unroll
                for (int nt = 0; nt < 4; nt++)
                    mma_f16(acc[mt][nt], a[mt], b0[nt], b1[nt]);
        }
        __syncthreads();
    }

    const int g = lane >> 2, tg = lane & 3;
    #pragma unroll
    for (int nt = 0; nt < 4; nt++) {
        int cc = wn + nt * 8 + tg * 2;
        #pragma unroll
        for (int mt = 0; mt < 4; mt++) {
            int r = bm + wm + mt * 16 + g;
            if (r < NA)
                *(__half2*)(Yh + (size_t)r * 128 + cc) =
                    __floats2half2_rn(acc[mt][nt][0], acc[mt][nt][1]);
            if (r + 8 < NA)
                *(__half2*)(Yh + (size_t)(r + 8) * 128 + cc) =
                    __floats2half2_rn(acc[mt][nt][2], acc[mt][nt][3]);
        }
    }
}

// ---- mega kernel 2: 4 proj GEMMs (blocks 0..1563) + degree hist (512) ----
#define GEMMB 1564   // 391*4
#define HISTB 512
__global__ void __launch_bounds__(256, 2) mega_proj_hist(
    const __half* __restrict__ xh, const __half* __restrict__ Wh,
    __half* __restrict__ fth,
    const int* __restrict__ r0, const int* __restrict__ r1,
    const int* __restrict__ r2, const int* __restrict__ r3,
    int* __restrict__ deg)
{
    int bid = blockIdx.x;
    if (bid < GEMMB) {
        int y = bid / 391;
        int bx = bid - y * 391;
        // y0: x_b@W_ab, y1: x_c@W_ac, y2: x_a@W_ba, y3: x_a@W_ca
        const __half* A = (y == 0) ? xh + 1ull * NROW * 256
                        : (y == 1) ? xh + 2ull * NROW * 256
                                   : xh;
        gemm_proj_body(A, Wh + (size_t)y * 256 * 128,
                       fth + (size_t)y * NROW * 128, bx);
    } else {
        int hb = bid - GEMMB;
        for (int i = hb * 256 + threadIdx.x; i < 4 * EDG; i += HISTB * 256) {
            int rel = i / EDG;
            int e   = i - rel * EDG;
            const int* row = (rel == 0) ? r0 : (rel == 1) ? r1 : (rel == 2) ? r2 : r3;
            atomicAdd(&deg[rel * NROW + row[e]], 1);
        }
    }
}

// ================= tf32 output GEMM (RNA on A) ============================
// out[N,128] = [agg | x] @ [wcat1 ; Wfold] + bias, K=384
__global__ void __launch_bounds__(256, 2) gemm_out(
    const float* __restrict__ aggbase,
    const float* __restrict__ xa, const float* __restrict__ xb,
    const float* __restrict__ xc,
    const unsigned* __restrict__ Wc1T, const unsigned* __restrict__ WfT,
    const float* __restrict__ ba, const float* __restrict__ bb,
    const float* __restrict__ bc, float* __restrict__ outbase)
{
    __shared__ float    As[2][128][20];
    __shared__ unsigned Bs[2][128][20];

    const int y = blockIdx.y;
    const float* A0 = aggbase + (size_t)y * SZ;
    const float* A1 = (y == 0) ? xa : (y == 1) ? xb : xc;
    const unsigned* B0T = Wc1T + (size_t)y * 128 * 128;
    const unsigned* B1T = WfT  + (size_t)y * 256 * 128;
    const float* bias = (y == 0) ? ba : (y == 1) ? bb : bc;
    float* Y = outbase + (size_t)y * NROW * 128;

    const int tid  = threadIdx.x;
    const int lane = tid & 31;
    const int w    = tid >> 5;
    const int bm   = blockIdx.x * 128;

    const int wm = (w >> 2) * 64;
    const int wn = (w & 3) * 32;

    const int a_mo = ((lane >> 3) & 1) * 8 + (lane & 7);
    const int a_ko = (lane >> 4) * 4;
    const int b_no = (lane >> 4) * 8 + (lane & 7);
    const int b_ko = ((lane >> 3) & 1) * 4;

    float acc[4][4][4];
    #pragma unroll
    for (int i = 0; i < 4; i++)
        #pragma unroll
        for (int j = 0; j < 4; j++)
            #pragma unroll
            for (int c = 0; c < 4; c++) acc[i][j][c] = 0.f;

    auto stage = [&](int buf, int k0) {
        const float* asrc; int ld, colb;
        if (k0 >= 128) { asrc = A1; ld = 256; colb = k0 - 128; }
        else           { asrc = A0; ld = 128; colb = k0; }
        #pragma unroll
        for (int i = 0; i < 2; i++) {
            int slot = tid + i * 256;
            int r = slot >> 2, c = (slot & 3) * 4;
            int grow = bm + r;
            const float* src = asrc + (size_t)(grow < NA ? grow : 0) * ld + colb + c;
            cpasync16(&As[buf][r][c], src, grow < NA ? 16 : 0);
        }
        const unsigned* bsrc; int ldb;
        if (k0 >= 128) { bsrc = B1T + (k0 - 128); ldb = 256; }
        else           { bsrc = B0T + k0;         ldb = 128; }
        #pragma unroll
        for (int i = 0; i < 2; i++) {
            int slot = tid + i * 256;
            int n = slot >> 2, c = (slot & 3) * 4;
            cpasync16(&Bs[buf][n][c], bsrc + (size_t)n * ldb + c, 16);
        }
        asm volatile("cp.async.commit_group;\n" ::);
    };

    stage(0, 0);

    for (int kt = 0; kt < 24; kt++) {
        if (kt + 1 < 24) {
            stage((kt + 1) & 1, (kt + 1) * 16);
            asm volatile("cp.async.wait_group 1;\n" ::);
        } else {
            asm volatile("cp.async.wait_group 0;\n" ::);
        }
        __syncthreads();

        const int buf = kt & 1;
        #pragma unroll
        for (int ks = 0; ks < 2; ks++) {
            const int k8 = ks * 8;
            unsigned a[4][4], b0[4], b1[4];
            #pragma unroll
            for (int mt = 0; mt < 4; mt++) {
                unsigned addr = (unsigned)__cvta_generic_to_shared(
                    &As[buf][wm + mt * 16 + a_mo][k8 + a_ko]);
                ldsm4(a[mt][0], a[mt][1], a[mt][2], a[mt][3], addr);
                #pragma unroll
                for (int r = 0; r < 4; r++)
                    a[mt][r] = f2tf(__uint_as_float(a[mt][r]));
            }
            #pragma unroll
            for (int np = 0; np < 2; np++) {
                unsigned addr = (unsigned)__cvta_generic_to_shared(
                    &Bs[buf][wn + np * 16 + b_no][k8 + b_ko]);
                ldsm4(b0[np * 2], b1[np * 2], b0[np * 2 + 1], b1[np * 2 + 1], addr);
            }
            #pragma unroll
            for (int mt = 0; mt < 4; mt++)
                #pragma unroll
                for (int nt = 0; nt < 4; nt++)
                    mma_tf32(acc[mt][nt], a[mt], b0[nt], b1[nt]);
        }
        __syncthreads();
    }

    const int g = lane >> 2, tg = lane & 3;
    #pragma unroll
    for (int nt = 0; nt < 4; nt++) {
        int cc = wn + nt * 8 + tg * 2;
        float bx = bias[cc], by = bias[cc + 1];
        #pragma unroll
        for (int mt = 0; mt < 4; mt++) {
            int r = bm + wm + mt * 16 + g;
            if (r < NA)
                *(float2*)(Y + (size_t)r * 128 + cc) =
                    make_float2(acc[mt][nt][0] + bx, acc[mt][nt][1] + by);
            if (r + 8 < NA)
                *(float2*)(Y + (size_t)(r + 8) * 128 + cc) =
                    make_float2(acc[mt][nt][2] + bx, acc[mt][nt][3] + by);
        }
    }
}

// ================= mega prep kernel =======================================
// sections: x->fp16 convert | W->fp16 copy | wc1 transpose | fold | uv+wv | zero deg
#define CONVB 2048
#define WHB   512
#define WC1B  192
#define FOLDB 384
#define UVB   1
#define ZEROB 782
__global__ void mega_prep(
    const float* __restrict__ xa, const float* __restrict__ xb,
    const float* __restrict__ xc, uint2* __restrict__ xh_u2,
    const float* __restrict__ Wab, const float* __restrict__ Wac,
    const float* __restrict__ Wba, const float* __restrict__ Wca,
    __half* __restrict__ Wh,
    const float* __restrict__ wca_, const float* __restrict__ wcb_,
    const float* __restrict__ wcc_, unsigned* __restrict__ Wc1T,
    const float* __restrict__ wsa, const float* __restrict__ wsb,
    const float* __restrict__ wsc, unsigned* __restrict__ WfT,
    const float* __restrict__ wq, const float* __restrict__ wk,
    const float* __restrict__ watt, float* __restrict__ uv,
    int* __restrict__ deg)
{
    int bid = blockIdx.x;
    int tid = threadIdx.x;

    if (bid < CONVB) {
        for (int i = bid * 256 + tid; i < 3 * XQ4; i += CONVB * 256) {
            int arr = i / XQ4;
            int off = i - arr * XQ4;
            const float* src = (arr == 0) ? xa : (arr == 1) ? xb : xc;
            float4 v = ((const float4*)src)[off];
            __half2 h0 = __floats2half2_rn(v.x, v.y);
            __half2 h1 = __floats2half2_rn(v.z, v.w);
            uint2 u;
            u.x = *(unsigned*)&h0;
            u.y = *(unsigned*)&h1;
            xh_u2[(size_t)arr * XQ4 + off] = u;
        }
        return;
    }
    bid -= CONVB;
    if (bid < WHB) {
        int rel = bid >> 7, blk = bid & 127;
        const float* W = (rel == 0) ? Wab : (rel == 1) ? Wac : (rel == 2) ? Wba : Wca;
        int idx = blk * 256 + tid;
        Wh[(size_t)rel * 32768 + idx] = __float2half(W[idx]);
        return;
    }
    bid -= WHB;
    if (bid < WC1B) {
        int m = bid / 64, blk = bid - m * 64;
        const float* wc = (m == 0) ? wca_ : (m == 1) ? wcb_ : wcc_;
        int idx = blk * 256 + tid;
        int k = idx >> 7, n = idx & 127;
        Wc1T[(size_t)m * 16384 + n * 128 + k] = f2tf(wc[k * 128 + n]);
        return;
    }
    bid -= WC1B;
    if (bid < FOLDB) {
        int m = bid >> 7, blk = bid & 127;
        const float* ws = (m == 0) ? wsa : (m == 1) ? wsb : wsc;
        const float* wc = ((m == 0) ? wca_ : (m == 1) ? wcb_ : wcc_) + 128 * 128;
        int idx = blk * 256 + tid;
        int k = idx >> 7, n = idx & 127;
        float s = 0.f;
        #pragma unroll 8
        for (int j = 0; j < 128; j++) s += ws[k * 128 + j] * wc[j * 128 + n];
        WfT[(size_t)m * 32768 + n * 256 + k] = f2tf(s);
        return;
    }
    bid -= FOLDB;
    if (bid < UVB) {
        // uv then wv (needs v) in one block
        if (tid < 128) {
            float s = 0.f;
            #pragma unroll
            for (int j = 0; j < 64; j++) s += wk[tid * 64 + j] * watt[j];
            uv[tid] = s;
        } else {
            int i = tid - 128;
            float s = 0.f;
            #pragma unroll
            for (int j = 0; j < 64; j++) s += wq[i * 64 + j] * watt[64 + j];
            uv[128 + i] = s;
        }
        __syncthreads();
        {
            const float* v = uv + 128;
            float s = 0.f;
            #pragma unroll 8
            for (int j = 0; j < 128; j++) s += wsa[tid * 128 + j] * v[j];
            uv[256 + tid] = s;
        }
        return;
    }
    bid -= UVB;
    {
        int i = bid * 256 + tid;
        if (i < 4 * NROW) deg[i] = 0;
    }
}

// ================= CSR: scan + scatter ====================================
__global__ void __launch_bounds__(1024) exscan4(const int* __restrict__ degbase,
                                                int* __restrict__ basebase,
                                                int* __restrict__ curbase)
{
    const int* deg = degbase + blockIdx.x * NROW;
    int* base = basebase + blockIdx.x * (NROW + 1);
    int* cur  = curbase  + blockIdx.x * NROW;

    __shared__ int wsum[32];
    __shared__ int carry;
    int tid = threadIdx.x, lane = tid & 31, wid = tid >> 5;
    if (tid == 0) carry = 0;
    __syncthreads();

    for (int start = 0; start < NROW; start += 1024) {
        int i = start + tid;
        int v = (i < NROW) ? deg[i] : 0;
        int x = v;
        #pragma unroll
        for (int off = 1; off < 32; off <<= 1) {
            int t = __shfl_up_sync(0xffffffffu, x, off);
            if (lane >= off) x += t;
        }
        if (lane == 31) wsum[wid] = x;
        __syncthreads();
        if (wid == 0) {
            int s = wsum[lane];
            #pragma unroll
            for (int off = 1; off < 32; off <<= 1) {
                int t = __shfl_up_sync(0xffffffffu, s, off);
                if (lane >= off) s += t;
            }
            wsum[lane] = s;
        }
        __syncthreads();
        int incl = x + (wid ? wsum[wid - 1] : 0) + carry;
        if (i < NROW) { base[i] = incl - v; cur[i] = incl - v; }
        __syncthreads();
        if (tid == 0) carry += wsum[31];
        __syncthreads();
    }
    if (threadIdx.x == 0) base[NROW] = carry;
}

__global__ void scatter4(const int* __restrict__ r0, const int* __restrict__ c0, const float* __restrict__ v0,
                         const int* __restrict__ r1, const int* __restrict__ c1, const float* __restrict__ v1,
                         const int* __restrict__ r2, const int* __restrict__ c2, const float* __restrict__ v2,
                         const int* __restrict__ r3, const int* __restrict__ c3, const float* __restrict__ v3,
                         int* __restrict__ curbase, int2* __restrict__ epackbase)
{
    const int* row; const int* col; const float* val;
    switch (blockIdx.y) {
        case 0: row = r0; col = c0; val = v0; break;
        case 1: row = r1; col = c1; val = v1; break;
        case 2: row = r2; col = c2; val = v2; break;
        default: row = r3; col = c3; val = v3; break;
    }
    int* cur = curbase + blockIdx.y * NROW;
    int2* ep = epackbase + (size_t)blockIdx.y * EDG;
    int i = blockIdx.x * blockDim.x + threadIdx.x;
    if (i >= EDG) return;
    int r = row[i];
    int pos = atomicAdd(&cur[r], 1);
    ep[pos] = make_int2(col[i], __float_as_int(val[i]));
}

// ================= gather (fp16 features) =================================
__device__ __forceinline__ float4 gather_row(
    const int2* __restrict__ ep, const int* __restrict__ base,
    int r, const __half* __restrict__ ft, int lane)
{
    int s = base[r], e = base[r + 1];
    float4 acc = make_float4(0.f, 0.f, 0.f, 0.f);
    int j = s;
    for (; j + 1 < e; j += 2) {
        int2 p0 = ep[j];
        int2 p1 = ep[j + 1];
        float va = __int_as_float(p0.y);
        float vb = __int_as_float(p1.y);
        const __half2* ra = (const __half2*)(ft + (size_t)p0.x * 128);
        const __half2* rb = (const __half2*)(ft + (size_t)p1.x * 128);
        float2 a0 = __half22float2(ra[lane * 2]);
        float2 a1 = __half22float2(ra[lane * 2 + 1]);
        float2 b0 = __half22float2(rb[lane * 2]);
        float2 b1 = __half22float2(rb[lane * 2 + 1]);
        acc.x += va * a0.x + vb * b0.x;
        acc.y += va * a0.y + vb * b0.y;
        acc.z += va * a1.x + vb * b1.x;
        acc.w += va * a1.y + vb * b1.y;
    }
    if (j < e) {
        int2 p = ep[j];
        float v = __int_as_float(p.y);
        const __half2* rp = (const __half2*)(ft + (size_t)p.x * 128);
        float2 l0 = __half22float2(rp[lane * 2]);
        float2 l1 = __half22float2(rp[lane * 2 + 1]);
        acc.x += v * l0.x; acc.y += v * l0.y;
        acc.z += v * l1.x; acc.w += v * l1.y;
    }
    return acc;
}

// y=0: rel0+rel1 gather + attention -> agga ; y=1: rel2 -> aggb ; y=2: rel3 -> aggc
__global__ void __launch_bounds__(256) gather_all(
    const int2* __restrict__ epack, const int* __restrict__ basebase,
    const __half* __restrict__ fth, const __half* __restrict__ xh,
    const float* __restrict__ uv, float* __restrict__ aggbase)
{
    int warp = (blockIdx.x * blockDim.x + threadIdx.x) >> 5;
    int lane = threadIdx.x & 31;
    if (warp >= NROW) return;

    if (blockIdx.y != 0) {
        int rel = 1 + blockIdx.y;    // 2 or 3
        float4 acc = gather_row(epack + (size_t)rel * EDG,
                                basebase + rel * (NROW + 1),
                                warp, fth + (size_t)rel * NROW * 128, lane);
        ((float4*)(aggbase + (size_t)blockIdx.y * SZ + (size_t)warp * 128))[lane] = acc;
        return;
    }

    float4 b = gather_row(epack, basebase, warp, fth, lane);
    float4 c = gather_row(epack + EDG, basebase + (NROW + 1), warp,
                          fth + (size_t)NROW * 128, lane);

    float4 u4 = ((const float4*)uv)[lane];
    // ds = x_a . wv  (xh_a fp16, wv fp32)
    const __half2* xrow = (const __half2*)(xh + (size_t)warp * 256);
    float4 w0 = ((const float4*)(uv + 256))[lane * 2];
    float4 w1 = ((const float4*)(uv + 256))[lane * 2 + 1];
    float2 q0 = __half22float2(xrow[lane * 4 + 0]);
    float2 q1 = __half22float2(xrow[lane * 4 + 1]);
    float2 q2 = __half22float2(xrow[lane * 4 + 2]);
    float2 q3 = __half22float2(xrow[lane * 4 + 3]);

    float db = b.x * u4.x + b.y * u4.y + b.z * u4.z + b.w * u4.w;
    float dc = c.x * u4.x + c.y * u4.y + c.z * u4.z + c.w * u4.w;
    float ds = q0.x * w0.x + q0.y * w0.y + q1.x * w0.z + q1.y * w0.w
             + q2.x * w1.x + q2.y * w1.y + q3.x * w1.z + q3.y * w1.w;

    #pragma unroll
    for (int o = 16; o; o >>= 1) {
        db += __shfl_xor_sync(0xffffffffu, db, o);
        dc += __shfl_xor_sync(0xffffffffu, dc, o);
        ds += __shfl_xor_sync(0xffffffffu, ds, o);
    }

    float eb = db + ds;
    float ec = dc + ds;
    eb = (eb > 0.f) ? eb : expm1f(eb);
    ec = (ec > 0.f) ? ec : expm1f(ec);
    float m  = fmaxf(eb, ec);
    float wb = expf(eb - m);
    float wc = expf(ec - m);
    float ab = wb / (wb + wc);
    float ac = 1.f - ab;

    float4 o4;
    o4.x = ab * b.x + ac * c.x;
    o4.y = ab * b.y + ac * c.y;
    o4.z = ab * b.z + ac * c.z;
    o4.w = ab * b.w + ac * c.w;
    ((float4*)(aggbase + (size_t)warp * 128))[lane] = o4;
}

// ================= launcher ===============================================
extern "C" void kernel_launch(void* const* d_in, const int* in_sizes, int n_in,
                              void* d_out, int out_size)
{
    const float* x_a       = (const float*)d_in[0];
    const float* x_b       = (const float*)d_in[1];
    const float* x_c       = (const float*)d_in[2];
    const int*   row_ab    = (const int*)d_in[3];
    const int*   col_ab    = (const int*)d_in[4];
    const float* val_ab    = (const float*)d_in[5];
    const int*   row_ac    = (const int*)d_in[6];
    const int*   col_ac    = (const int*)d_in[7];
    const float* val_ac    = (const float*)d_in[8];
    const int*   row_ba    = (const int*)d_in[9];
    const int*   col_ba    = (const int*)d_in[10];
    const float* val_ba    = (const float*)d_in[11];
    const int*   row_ca    = (const int*)d_in[12];
    const int*   col_ca    = (const int*)d_in[13];
    const float* val_ca    = (const float*)d_in[14];
    const float* w_self_a  = (const float*)d_in[15];
    const float* w_self_b  = (const float*)d_in[16];
    const float* w_self_c  = (const float*)d_in[17];
    const float* W_ab      = (const float*)d_in[18];
    const float* W_ac      = (const float*)d_in[19];
    const float* W_ba      = (const float*)d_in[20];
    const float* W_ca      = (const float*)d_in[21];
    const float* bias_a    = (const float*)d_in[22];
    const float* bias_b    = (const float*)d_in[23];
    const float* bias_c    = (const float*)d_in[24];
    const float* w_cat_a   = (const float*)d_in[25];
    const float* w_cat_b   = (const float*)d_in[26];
    const float* w_cat_c   = (const float*)d_in[27];
    const float* w_query_a = (const float*)d_in[28];
    const float* w_keys_a  = (const float*)d_in[29];
    const float* w_att_a   = (const float*)d_in[30];

    float* scratch = nullptr;
    cudaGetSymbolAddress((void**)&scratch, g_scratch);

    float*    aggbase = scratch;
    __half*   fth     = (__half*)(scratch + OFF_FTH);
    __half*   xh      = (__half*)(scratch + OFF_XH);
    __half*   Wh      = (__half*)(scratch + OFF_WH);
    unsigned* Wc1T    = (unsigned*)(scratch + OFF_WC1);
    unsigned* WfT     = (unsigned*)(scratch + OFF_WF);
    float*    uv      = scratch + OFF_UV;
    int*      deg     = (int*)(scratch + OFF_DEG);
    int*      base    = (int*)(scratch + OFF_BASE);
    int*      cur     = (int*)(scratch + OFF_CUR);
    int2*     epack   = (int2*)(scratch + OFF_EPACK);

    float* out = (float*)d_out;

    const int PREPB = CONVB + WHB + WC1B + FOLDB + UVB + ZEROB;   // 3919
    const int EB    = (EDG + 255) / 256;                          // 3125
    const int GWB   = (NROW * 32 + 255) / 256;                    // 6250

    // 1. prep: x->fp16, W->fp16, wc1T, fold, uv/wv, zero deg
    mega_prep<<<PREPB, 256>>>(x_a, x_b, x_c, (uint2*)xh,
                              W_ab, W_ac, W_ba, W_ca, Wh,
                              w_cat_a, w_cat_b, w_cat_c, Wc1T,
                              w_self_a, w_self_b, w_self_c, WfT,
                              w_query_a, w_keys_a, w_att_a, uv, deg);

    // 2. proj GEMMs (fp16) + degree histogram in one grid
    mega_proj_hist<<<GEMMB + HISTB, 256>>>(xh, Wh, fth,
                                           row_ab, row_ac, row_ba, row_ca, deg);

    // 3-4. CSR scan + scatter
    exscan4<<<4, 1024>>>(deg, base, cur);
    scatter4<<<dim3(EB, 4), 256>>>(row_ab, col_ab, val_ab,
                                   row_ac, col_ac, val_ac,
                                   row_ba, col_ba, val_ba,
                                   row_ca, col_ca, val_ca,
                                   cur, epack);

    // 5. gathers + attention (one launch)
    gather_all<<<dim3(GWB, 3), 256>>>(epack, base, fth, xh, uv, aggbase);

    // 6. output GEMMs (tf32, RNA)
    gemm_out<<<dim3(391, 3), 256>>>(aggbase, x_a, x_b, x_c, Wc1T, WfT,
                                    bias_a, bias_b, bias_c, out);
}

// round 9
// speedup vs baseline: 4.9325x; 1.1802x over previous
#include <cuda_runtime.h>
#include <cuda_fp16.h>
#include <cstdint>
#include <cstddef>

// ---------------- problem constants ----------------
#define NA 50000
#define NROW 50000
#define EDG 800000
#define SZ (50000 * 128)        // floats per [N,128] fp32-equivalent slot
#define XQ4 3200000             // float4 count per x array (50000*256/4)

// scratch layout (float units):
//  0          : aggh  = 3 x [N,128] fp16   (1.5 slots, rounded to 2)
//  2*SZ       : fth   = 4 x [N,128] fp16   (2 slots exactly)
//  4*SZ       : xh    = 3 x [N,256] fp16   (3 slots exactly)
#define OFF_AGGH   0ull
#define OFF_FTH    (2ull * SZ)
#define OFF_XH     (4ull * SZ)
#define W_OFF      (7ull * SZ)
#define OFF_WH     (W_OFF)                        // 4*256*128 halves = 65536 FLOATS
#define OFF_WCOMB  (OFF_WH + 65536)               // 3*384*128 halves = 73728 floats
#define OFF_UV     (OFF_WCOMB + 73728)            // 512 floats
#define OFF_DEG    (OFF_UV   + 512)
#define OFF_BASE   (OFF_DEG  + 4*50000)
#define OFF_CUR    (OFF_BASE + 4*50004)
#define OFF_EPACK  (((OFF_CUR + 4*50000) + 1) & ~1ull)
#define SCRATCH_TOTAL (OFF_EPACK + 4ull*EDG*2)

__device__ float g_scratch[SCRATCH_TOTAL];

// ---------------- helpers ----------------
__device__ __forceinline__ void ldsm4(unsigned &r0, unsigned &r1, unsigned &r2,
                                      unsigned &r3, unsigned addr) {
    asm volatile("ldmatrix.sync.aligned.m8n8.x4.shared.b16 {%0,%1,%2,%3}, [%4];"
                 : "=r"(r0), "=r"(r1), "=r"(r2), "=r"(r3) : "r"(addr));
}

__device__ __forceinline__ void ldsm4t(unsigned &r0, unsigned &r1, unsigned &r2,
                                       unsigned &r3, unsigned addr) {
    asm volatile("ldmatrix.sync.aligned.m8n8.x4.trans.shared.b16 {%0,%1,%2,%3}, [%4];"
                 : "=r"(r0), "=r"(r1), "=r"(r2), "=r"(r3) : "r"(addr));
}

__device__ __forceinline__ void mma_f16(float c[4], const unsigned a[4],
                                        unsigned b0, unsigned b1) {
    asm volatile(
        "mma.sync.aligned.m16n8k16.row.col.f32.f16.f16.f32 "
        "{%0,%1,%2,%3}, {%4,%5,%6,%7}, {%8,%9}, {%0,%1,%2,%3};"
        : "+f"(c[0]), "+f"(c[1]), "+f"(c[2]), "+f"(c[3])
        : "r"(a[0]), "r"(a[1]), "r"(a[2]), "r"(a[3]), "r"(b0), "r"(b1));
}

__device__ __forceinline__ void cpasync16(void* sdst, const void* gsrc, int nbytes) {
    unsigned s = (unsigned)__cvta_generic_to_shared(sdst);
    asm volatile("cp.async.cg.shared.global [%0], [%1], 16, %2;\n"
                 :: "r"(s), "l"(gsrc), "r"(nbytes));
}

// ================= fp16 GEMM body (K-tiles of 32) =========================
template<int NKT, bool HOUT, bool SPLIT>
__device__ __forceinline__ void gemm_f16_body(
    const __half* __restrict__ A0, int lda0,
    const __half* __restrict__ A1, int lda1,
    const __half* __restrict__ B,                     // [K][128] row-major
    const float* __restrict__ bias,
    __half* __restrict__ Yh, float* __restrict__ Yf, int bx)
{
    __shared__ __half As[2][128][40];    // 32 k + 8 pad
    __shared__ __half Bs[2][32][136];    // [k][n], 128 n + 8 pad

    const int tid  = threadIdx.x;
    const int lane = tid & 31;
    const int w    = tid >> 5;
    const int bm   = bx * 128;

    const int wm = (w >> 2) * 64;
    const int wn = (w & 3) * 32;

    float acc[4][4][4];
    #pragma unroll
    for (int i = 0; i < 4; i++)
        #pragma unroll
        for (int j = 0; j < 4; j++)
            #pragma unroll
            for (int c = 0; c < 4; c++) acc[i][j][c] = 0.f;

    auto stage = [&](int buf, int k0) {
        const __half* asrc; int ld, col;
        if (SPLIT && k0 >= 128) { asrc = A1; ld = lda1; col = k0 - 128; }
        else                    { asrc = A0; ld = lda0; col = k0; }
        #pragma unroll
        for (int i = 0; i < 2; i++) {
            int slot = tid + i * 256;
            int r = slot >> 2, c = (slot & 3) * 8;
            int grow = bm + r;
            const __half* src = asrc + (size_t)(grow < NA ? grow : 0) * ld + col + c;
            cpasync16(&As[buf][r][c], src, grow < NA ? 16 : 0);
        }
        #pragma unroll
        for (int i = 0; i < 2; i++) {
            int slot = tid + i * 256;
            int r = slot >> 4, c = (slot & 15) * 8;
            cpasync16(&Bs[buf][r][c], B + (size_t)(k0 + r) * 128 + c, 16);
        }
        asm volatile("cp.async.commit_group;\n" ::);
    };

    stage(0, 0);

    for (int kt = 0; kt < NKT; kt++) {
        if (kt + 1 < NKT) {
            stage((kt + 1) & 1, (kt + 1) * 32);
            asm volatile("cp.async.wait_group 1;\n" ::);
        } else {
            asm volatile("cp.async.wait_group 0;\n" ::);
        }
        __syncthreads();

        const int buf = kt & 1;
        #pragma unroll
        for (int ks = 0; ks < 2; ks++) {
            const int k16 = ks * 16;
            unsigned a[4][4], b0[4], b1[4];
            #pragma unroll
            for (int mt = 0; mt < 4; mt++) {
                unsigned addr = (unsigned)__cvta_generic_to_shared(
                    &As[buf][wm + mt * 16 + (lane & 15)][k16 + (lane >> 4) * 8]);
                ldsm4(a[mt][0], a[mt][1], a[mt][2], a[mt][3], addr);
            }
            #pragma unroll
            for (int np = 0; np < 2; np++) {
                unsigned addr = (unsigned)__cvta_generic_to_shared(
                    &Bs[buf][k16 + (lane & 15)][wn + np * 16 + (lane >> 4) * 8]);
                ldsm4t(b0[np * 2], b1[np * 2], b0[np * 2 + 1], b1[np * 2 + 1], addr);
            }
            #pragma unroll
            for (int mt = 0; mt < 4; mt++)
                #pragma unroll
                for (int nt = 0; nt < 4; nt++)
                    mma_f16(acc[mt][nt], a[mt], b0[nt], b1[nt]);
        }
        __syncthreads();
    }

    const int g = lane >> 2, tg = lane & 3;
    #pragma unroll
    for (int nt = 0; nt < 4; nt++) {
        int cc = wn + nt * 8 + tg * 2;
        float bx0 = HOUT ? 0.f : bias[cc];
        float bx1 = HOUT ? 0.f : bias[cc + 1];
        #pragma unroll
        for (int mt = 0; mt < 4; mt++) {
            int r = bm + wm + mt * 16 + g;
            if (r < NA) {
                if (HOUT)
                    *(__half2*)(Yh + (size_t)r * 128 + cc) =
                        __floats2half2_rn(acc[mt][nt][0], acc[mt][nt][1]);
                else
                    *(float2*)(Yf + (size_t)r * 128 + cc) =
                        make_float2(acc[mt][nt][0] + bx0, acc[mt][nt][1] + bx1);
            }
            if (r + 8 < NA) {
                if (HOUT)
                    *(__half2*)(Yh + (size_t)(r + 8) * 128 + cc) =
                        __floats2half2_rn(acc[mt][nt][2], acc[mt][nt][3]);
                else
                    *(float2*)(Yf + (size_t)(r + 8) * 128 + cc) =
                        make_float2(acc[mt][nt][2] + bx0, acc[mt][nt][3] + bx1);
            }
        }
    }
}

// ---- proj GEMMs (4) + degree hist in one grid ----
#define GEMMB 1564   // 391*4
#define HISTB 512
__global__ void __launch_bounds__(256, 2) mega_proj_hist(
    const __half* __restrict__ xh, const __half* __restrict__ Wh,
    __half* __restrict__ fth,
    const int* __restrict__ r0, const int* __restrict__ r1,
    const int* __restrict__ r2, const int* __restrict__ r3,
    int* __restrict__ deg)
{
    int bid = blockIdx.x;
    if (bid < GEMMB) {
        int y = bid / 391;
        int bx = bid - y * 391;
        // y0: x_b@W_ab, y1: x_c@W_ac, y2: x_a@W_ba, y3: x_a@W_ca
        const __half* A = (y == 0) ? xh + 1ull * NROW * 256
                        : (y == 1) ? xh + 2ull * NROW * 256
                                   : xh;
        gemm_f16_body<8, true, false>(A, 256, nullptr, 0,
                                      Wh + (size_t)y * 256 * 128, nullptr,
                                      fth + (size_t)y * NROW * 128, nullptr, bx);
    } else {
        int hb = bid - GEMMB;
        for (int i = hb * 256 + threadIdx.x; i < 4 * EDG; i += HISTB * 256) {
            int rel = i / EDG;
            int e   = i - rel * EDG;
            const int* row = (rel == 0) ? r0 : (rel == 1) ? r1 : (rel == 2) ? r2 : r3;
            atomicAdd(&deg[rel * NROW + row[e]], 1);
        }
    }
}

// ---- output GEMMs: [aggh | xh] @ Wcomb[384][128] + bias, fp16, K=384 ----
__global__ void __launch_bounds__(256, 2) gemm_out_f16(
    const __half* __restrict__ aggh, const __half* __restrict__ xh,
    const __half* __restrict__ Wcomb,
    const float* __restrict__ ba, const float* __restrict__ bb,
    const float* __restrict__ bc, float* __restrict__ outbase)
{
    int y = blockIdx.y;
    const float* bias = (y == 0) ? ba : (y == 1) ? bb : bc;
    gemm_f16_body<12, false, true>(
        aggh + (size_t)y * NROW * 128, 128,
        xh   + (size_t)y * NROW * 256, 256,
        Wcomb + (size_t)y * 384 * 128,
        bias, nullptr, outbase + (size_t)y * NROW * 128, blockIdx.x);
}

// ================= mega prep kernel =======================================
#define CONVB 2048
#define WHB   512
#define WC1B  192
#define FOLDB 384
#define UVB   1
#define ZEROB 782
__global__ void mega_prep(
    const float* __restrict__ xa, const float* __restrict__ xb,
    const float* __restrict__ xc, uint2* __restrict__ xh_u2,
    const float* __restrict__ Wab, const float* __restrict__ Wac,
    const float* __restrict__ Wba, const float* __restrict__ Wca,
    __half* __restrict__ Wh,
    const float* __restrict__ wca_, const float* __restrict__ wcb_,
    const float* __restrict__ wcc_,
    const float* __restrict__ wsa, const float* __restrict__ wsb,
    const float* __restrict__ wsc, __half* __restrict__ Wcomb,
    const float* __restrict__ wq, const float* __restrict__ wk,
    const float* __restrict__ watt, float* __restrict__ uv,
    int* __restrict__ deg)
{
    int bid = blockIdx.x;
    int tid = threadIdx.x;

    if (bid < CONVB) {
        for (int i = bid * 256 + tid; i < 3 * XQ4; i += CONVB * 256) {
            int arr = i / XQ4;
            int off = i - arr * XQ4;
            const float* src = (arr == 0) ? xa : (arr == 1) ? xb : xc;
            float4 v = ((const float4*)src)[off];
            __half2 h0 = __floats2half2_rn(v.x, v.y);
            __half2 h1 = __floats2half2_rn(v.z, v.w);
            uint2 u;
            u.x = *(unsigned*)&h0;
            u.y = *(unsigned*)&h1;
            xh_u2[(size_t)arr * XQ4 + off] = u;
        }
        return;
    }
    bid -= CONVB;
    if (bid < WHB) {
        int rel = bid >> 7, blk = bid & 127;
        const float* W = (rel == 0) ? Wab : (rel == 1) ? Wac : (rel == 2) ? Wba : Wca;
        int idx = blk * 256 + tid;
        Wh[(size_t)rel * 32768 + idx] = __float2half(W[idx]);
        return;
    }
    bid -= WHB;
    if (bid < WC1B) {
        // w_cat rows 0..127 -> Wcomb rows 0..127 (fp16, natural [k][n])
        int m = bid / 64, blk = bid - m * 64;
        const float* wc = (m == 0) ? wca_ : (m == 1) ? wcb_ : wcc_;
        int idx = blk * 256 + tid;   // 0..16383
        Wcomb[(size_t)m * 49152 + idx] = __float2half(wc[idx]);
        return;
    }
    bid -= WC1B;
    if (bid < FOLDB) {
        // Wfold[k][n] = sum_j wself[k][j]*wcat[128+j][n] -> Wcomb rows 128..383
        int m = bid >> 7, blk = bid & 127;
        const float* ws = (m == 0) ? wsa : (m == 1) ? wsb : wsc;
        const float* wc = ((m == 0) ? wca_ : (m == 1) ? wcb_ : wcc_) + 128 * 128;
        int idx = blk * 256 + tid;   // 0..32767
        int k = idx >> 7, n = idx & 127;
        float s = 0.f;
        #pragma unroll 8
        for (int j = 0; j < 128; j++) s += ws[k * 128 + j] * wc[j * 128 + n];
        Wcomb[(size_t)m * 49152 + (128 + k) * 128 + n] = __float2half(s);
        return;
    }
    bid -= FOLDB;
    if (bid < UVB) {
        if (tid < 128) {
            float s = 0.f;
            #pragma unroll
            for (int j = 0; j < 64; j++) s += wk[tid * 64 + j] * watt[j];
            uv[tid] = s;
        } else {
            int i = tid - 128;
            float s = 0.f;
            #pragma unroll
            for (int j = 0; j < 64; j++) s += wq[i * 64 + j] * watt[64 + j];
            uv[128 + i] = s;
        }
        __syncthreads();
        {
            const float* v = uv + 128;
            float s = 0.f;
            #pragma unroll 8
            for (int j = 0; j < 128; j++) s += wsa[tid * 128 + j] * v[j];
            uv[256 + tid] = s;
        }
        return;
    }
    bid -= UVB;
    {
        int i = bid * 256 + tid;
        if (i < 4 * NROW) deg[i] = 0;
    }
}

// ================= CSR: scan + scatter ====================================
__global__ void __launch_bounds__(1024) exscan4(const int* __restrict__ degbase,
                                                int* __restrict__ basebase,
                                                int* __restrict__ curbase)
{
    const int* deg = degbase + blockIdx.x * NROW;
    int* base = basebase + blockIdx.x * (NROW + 1);
    int* cur  = curbase  + blockIdx.x * NROW;

    __shared__ int wsum[32];
    __shared__ int carry;
    int tid = threadIdx.x, lane = tid & 31, wid = tid >> 5;
    if (tid == 0) carry = 0;
    __syncthreads();

    for (int start = 0; start < NROW; start += 1024) {
        int i = start + tid;
        int v = (i < NROW) ? deg[i] : 0;
        int x = v;
        #pragma unroll
        for (int off = 1; off < 32; off <<= 1) {
            int t = __shfl_up_sync(0xffffffffu, x, off);
            if (lane >= off) x += t;
        }
        if (lane == 31) wsum[wid] = x;
        __syncthreads();
        if (wid == 0) {
            int s = wsum[lane];
            #pragma unroll
            for (int off = 1; off < 32; off <<= 1) {
                int t = __shfl_up_sync(0xffffffffu, s, off);
                if (lane >= off) s += t;
            }
            wsum[lane] = s;
        }
        __syncthreads();
        int incl = x + (wid ? wsum[wid - 1] : 0) + carry;
        if (i < NROW) { base[i] = incl - v; cur[i] = incl - v; }
        __syncthreads();
        if (tid == 0) carry += wsum[31];
        __syncthreads();
    }
    if (threadIdx.x == 0) base[NROW] = carry;
}

// 2 independent edges per thread for latency overlap
#define EHALF (EDG / 2)
__global__ void scatter4(const int* __restrict__ r0, const int* __restrict__ c0, const float* __restrict__ v0,
                         const int* __restrict__ r1, const int* __restrict__ c1, const float* __restrict__ v1,
                         const int* __restrict__ r2, const int* __restrict__ c2, const float* __restrict__ v2,
                         const int* __restrict__ r3, const int* __restrict__ c3, const float* __restrict__ v3,
                         int* __restrict__ curbase, int2* __restrict__ epackbase)
{
    const int* row; const int* col; const float* val;
    switch (blockIdx.y) {
        case 0: row = r0; col = c0; val = v0; break;
        case 1: row = r1; col = c1; val = v1; break;
        case 2: row = r2; col = c2; val = v2; break;
        default: row = r3; col = c3; val = v3; break;
    }
    int* cur = curbase + blockIdx.y * NROW;
    int2* ep = epackbase + (size_t)blockIdx.y * EDG;
    int i = blockIdx.x * blockDim.x + threadIdx.x;
    if (i >= EHALF) return;
    int ra = row[i],         rb = row[i + EHALF];
    int ca = col[i],         cb = col[i + EHALF];
    float va = val[i],       vb = val[i + EHALF];
    int pa = atomicAdd(&cur[ra], 1);
    int pb = atomicAdd(&cur[rb], 1);
    ep[pa] = make_int2(ca, __float_as_int(va));
    ep[pb] = make_int2(cb, __float_as_int(vb));
}

// ================= gather (fp16 features, uint2 per lane) =================
__device__ __forceinline__ void edge_accum(float4& acc, float v,
                                           const __half* __restrict__ ft,
                                           int c, int lane)
{
    uint2 u = ((const uint2*)(ft + (size_t)c * 128))[lane];
    float2 l0 = __half22float2(*(__half2*)&u.x);
    float2 l1 = __half22float2(*(__half2*)&u.y);
    acc.x += v * l0.x; acc.y += v * l0.y;
    acc.z += v * l1.x; acc.w += v * l1.y;
}

__device__ __forceinline__ float4 gather_row(
    const int2* __restrict__ ep, const int* __restrict__ base,
    int r, const __half* __restrict__ ft, int lane)
{
    int s = base[r], e = base[r + 1];
    float4 acc = make_float4(0.f, 0.f, 0.f, 0.f);
    int j = s;
    for (; j + 3 < e; j += 4) {
        int2 p0 = ep[j],     p1 = ep[j + 1];
        int2 p2 = ep[j + 2], p3 = ep[j + 3];
        edge_accum(acc, __int_as_float(p0.y), ft, p0.x, lane);
        edge_accum(acc, __int_as_float(p1.y), ft, p1.x, lane);
        edge_accum(acc, __int_as_float(p2.y), ft, p2.x, lane);
        edge_accum(acc, __int_as_float(p3.y), ft, p3.x, lane);
    }
    for (; j < e; j++) {
        int2 p = ep[j];
        edge_accum(acc, __int_as_float(p.y), ft, p.x, lane);
    }
    return acc;
}

// y=0: rel0+rel1 gather + attention -> aggh[0] ; y=1: rel2 -> aggh[1] ; y=2: rel3 -> aggh[2]
__global__ void __launch_bounds__(256) gather_all(
    const int2* __restrict__ epack, const int* __restrict__ basebase,
    const __half* __restrict__ fth, const __half* __restrict__ xh,
    const float* __restrict__ uv, __half* __restrict__ aggh)
{
    int warp = (blockIdx.x * blockDim.x + threadIdx.x) >> 5;
    int lane = threadIdx.x & 31;
    if (warp >= NROW) return;

    if (blockIdx.y != 0) {
        int rel = 1 + blockIdx.y;    // 2 or 3
        float4 a = gather_row(epack + (size_t)rel * EDG,
                              basebase + rel * (NROW + 1),
                              warp, fth + (size_t)rel * NROW * 128, lane);
        __half2 h0 = __floats2half2_rn(a.x, a.y);
        __half2 h1 = __floats2half2_rn(a.z, a.w);
        uint2 u; u.x = *(unsigned*)&h0; u.y = *(unsigned*)&h1;
        ((uint2*)(aggh + (size_t)blockIdx.y * NROW * 128 + (size_t)warp * 128))[lane] = u;
        return;
    }

    float4 b = gather_row(epack, basebase, warp, fth, lane);
    float4 c = gather_row(epack + EDG, basebase + (NROW + 1), warp,
                          fth + (size_t)NROW * 128, lane);

    float4 u4 = ((const float4*)uv)[lane];
    const __half2* xrow = (const __half2*)(xh + (size_t)warp * 256);
    float4 w0 = ((const float4*)(uv + 256))[lane * 2];
    float4 w1 = ((const float4*)(uv + 256))[lane * 2 + 1];
    float2 q0 = __half22float2(xrow[lane * 4 + 0]);
    float2 q1 = __half22float2(xrow[lane * 4 + 1]);
    float2 q2 = __half22float2(xrow[lane * 4 + 2]);
    float2 q3 = __half22float2(xrow[lane * 4 + 3]);

    float db = b.x * u4.x + b.y * u4.y + b.z * u4.z + b.w * u4.w;
    float dc = c.x * u4.x + c.y * u4.y + c.z * u4.z + c.w * u4.w;
    float ds = q0.x * w0.x + q0.y * w0.y + q1.x * w0.z + q1.y * w0.w
             + q2.x * w1.x + q2.y * w1.y + q3.x * w1.z + q3.y * w1.w;

    #pragma unroll
    for (int o = 16; o; o >>= 1) {
        db += __shfl_xor_sync(0xffffffffu, db, o);
        dc += __shfl_xor_sync(0xffffffffu, dc, o);
        ds += __shfl_xor_sync(0xffffffffu, ds, o);
    }

    float eb = db + ds;
    float ec = dc + ds;
    eb = (eb > 0.f) ? eb : expm1f(eb);
    ec = (ec > 0.f) ? ec : expm1f(ec);
    float m  = fmaxf(eb, ec);
    float wb = expf(eb - m);
    float wc = expf(ec - m);
    float ab = wb / (wb + wc);
    float ac = 1.f - ab;

    float4 o4;
    o4.x = ab * b.x + ac * c.x;
    o4.y = ab * b.y + ac * c.y;
    o4.z = ab * b.z + ac * c.z;
    o4.w = ab * b.w + ac * c.w;
    __half2 h0 = __floats2half2_rn(o4.x, o4.y);
    __half2 h1 = __floats2half2_rn(o4.z, o4.w);
    uint2 u; u.x = *(unsigned*)&h0; u.y = *(unsigned*)&h1;
    ((uint2*)(aggh + (size_t)warp * 128))[lane] = u;
}

// ================= launcher ===============================================
extern "C" void kernel_launch(void* const* d_in, const int* in_sizes, int n_in,
                              void* d_out, int out_size)
{
    const float* x_a       = (const float*)d_in[0];
    const float* x_b       = (const float*)d_in[1];
    const float* x_c       = (const float*)d_in[2];
    const int*   row_ab    = (const int*)d_in[3];
    const int*   col_ab    = (const int*)d_in[4];
    const float* val_ab    = (const float*)d_in[5];
    const int*   row_ac    = (const int*)d_in[6];
    const int*   col_ac    = (const int*)d_in[7];
    const float* val_ac    = (const float*)d_in[8];
    const int*   row_ba    = (const int*)d_in[9];
    const int*   col_ba    = (const int*)d_in[10];
    const float* val_ba    = (const float*)d_in[11];
    const int*   row_ca    = (const int*)d_in[12];
    const int*   col_ca    = (const int*)d_in[13];
    const float* val_ca    = (const float*)d_in[14];
    const float* w_self_a  = (const float*)d_in[15];
    const float* w_self_b  = (const float*)d_in[16];
    const float* w_self_c  = (const float*)d_in[17];
    const float* W_ab      = (const float*)d_in[18];
    const float* W_ac      = (const float*)d_in[19];
    const float* W_ba      = (const float*)d_in[20];
    const float* W_ca      = (const float*)d_in[21];
    const float* bias_a    = (const float*)d_in[22];
    const float* bias_b    = (const float*)d_in[23];
    const float* bias_c    = (const float*)d_in[24];
    const float* w_cat_a   = (const float*)d_in[25];
    const float* w_cat_b   = (const float*)d_in[26];
    const float* w_cat_c   = (const float*)d_in[27];
    const float* w_query_a = (const float*)d_in[28];
    const float* w_keys_a  = (const float*)d_in[29];
    const float* w_att_a   = (const float*)d_in[30];

    float* scratch = nullptr;
    cudaGetSymbolAddress((void**)&scratch, g_scratch);

    __half*   aggh    = (__half*)(scratch + OFF_AGGH);
    __half*   fth     = (__half*)(scratch + OFF_FTH);
    __half*   xh      = (__half*)(scratch + OFF_XH);
    __half*   Wh      = (__half*)(scratch + OFF_WH);
    __half*   Wcomb   = (__half*)(scratch + OFF_WCOMB);
    float*    uv      = scratch + OFF_UV;
    int*      deg     = (int*)(scratch + OFF_DEG);
    int*      base    = (int*)(scratch + OFF_BASE);
    int*      cur     = (int*)(scratch + OFF_CUR);
    int2*     epack   = (int2*)(scratch + OFF_EPACK);

    float* out = (float*)d_out;

    const int PREPB = CONVB + WHB + WC1B + FOLDB + UVB + ZEROB;
    const int SCB   = (EHALF + 255) / 256;           // 1563
    const int GWB   = (NROW * 32 + 255) / 256;       // 6250

    // 1. prep
    mega_prep<<<PREPB, 256>>>(x_a, x_b, x_c, (uint2*)xh,
                              W_ab, W_ac, W_ba, W_ca, Wh,
                              w_cat_a, w_cat_b, w_cat_c,
                              w_self_a, w_self_b, w_self_c, Wcomb,
                              w_query_a, w_keys_a, w_att_a, uv, deg);

    // 2. proj GEMMs (fp16) + degree histogram
    mega_proj_hist<<<GEMMB + HISTB, 256>>>(xh, Wh, fth,
                                           row_ab, row_ac, row_ba, row_ca, deg);

    // 3-4. CSR scan + scatter (2 edges/thread)
    exscan4<<<4, 1024>>>(deg, base, cur);
    scatter4<<<dim3(SCB, 4), 256>>>(row_ab, col_ab, val_ab,
                                    row_ac, col_ac, val_ac,
                                    row_ba, col_ba, val_ba,
                                    row_ca, col_ca, val_ca,
                                    cur, epack);

    // 5. gathers + attention -> fp16 agg
    gather_all<<<dim3(GWB, 3), 256>>>(epack, base, fth, xh, uv, aggh);

    // 6. output GEMMs (fp16, K=384)
    gemm_out_f16<<<dim3(391, 3), 256>>>(aggh, xh, Wcomb,
                                        bias_a, bias_b, bias_c, out);
}